// round 10
// baseline (speedup 1.0000x reference)
#include <cuda_runtime.h>
#include <cuda.h>
#include <cuda_fp16.h>
#include <math.h>
#include <stdint.h>

#define BB 2
#define SS 2048
#define DM 1024
#define DI 2048
#define DSTATE 16
#define RANK 64
#define MM (BB*SS)   /* 4096 rows (b,s) */

// ---------------- scratch (static device globals; no runtime allocation) ----------------
__device__ float  g_xf32[(size_t)MM * DI];      // GEMM1 x-branch, [m][d] fp32
__device__ __half g_zh[(size_t)MM * DI];        // GEMM1 z-branch, [m][d] fp16
__device__ __half g_xbch[(size_t)MM * DI];      // conv+silu (u), [m][d] fp16
__device__ float  g_params[(size_t)MM * 96];    // [m][96]  (delta_in | b | c)
__device__ __half g_dinh[(size_t)MM * RANK];    // fp16 delta_in for delta mma
__device__ float  g_delta[(size_t)MM * DI];     // softplus delta, [m][d]

// fp16 operands for tensor-core GEMMs
__device__ __half g_A1h[(size_t)MM * DM];
__device__ __half g_B1h[(size_t)(2*DI) * DM];   // Win^T [N=4096][K=1024]
__device__ __half g_A3h[(size_t)MM * DI];       // gated y [4096][2048]
__device__ __half g_B3h[(size_t)DM * DI];       // Wout^T [N=1024][K=2048]
__device__ __half g_Wxh[(size_t)96 * DI];       // Wx^T  [96][2048]
__device__ __half g_Wdth[(size_t)DI * RANK];    // Wdt^T [2048][64]

// ================= low-level helpers =================
__device__ __forceinline__ uint32_t smem_to_u32(const void* smem_ptr) {
    uint32_t addr;
    asm("{ .reg .u64 tmp; cvta.to.shared.u64 tmp, %1; cvt.u32.u64 %0, tmp; }"
        : "=r"(addr) : "l"(smem_ptr));
    return addr;
}
#define CP_ASYNC16(saddr, gaddr) \
    asm volatile("cp.async.cg.shared.global [%0], [%1], 16;" :: "r"(saddr), "l"(gaddr))
#define CP_COMMIT() asm volatile("cp.async.commit_group;" ::: "memory")
#define CP_WAIT(n)  asm volatile("cp.async.wait_group %0;" :: "n"(n) : "memory")

#define MBARRIER_INIT(mbar, count) \
    asm volatile("mbarrier.init.shared.b64 [%0], %1;" \
        :: "r"((uint32_t)(mbar)), "r"((uint32_t)(count)) : "memory")
#define MBARRIER_EXPECT_TX(mbar, tx) \
    asm volatile("mbarrier.arrive.expect_tx.shared.b64 _, [%0], %1;" \
        :: "r"((uint32_t)(mbar)), "r"((uint32_t)(tx)) : "memory")
#define TMA_LOAD_2D(dst, tmap, x, y, mbar) \
    asm volatile("cp.async.bulk.tensor.2d.shared::cta.global.tile.mbarrier::complete_tx::bytes " \
        "[%0], [%1, {%2, %3}], [%4];" \
        :: "r"((uint32_t)(dst)), "l"(tmap), "r"((int)(x)), "r"((int)(y)), "r"((uint32_t)(mbar)) : "memory")

#define MBARRIER_WAIT_PARITY(mbar_smem_addr, phase_parity) do { \
    uint32_t _mbar = (uint32_t)(mbar_smem_addr); \
    uint32_t _parity = (uint32_t)(phase_parity); \
    uint32_t _done; \
    asm volatile( \
        "{\n\t.reg .pred p;\n\t" \
        "mbarrier.try_wait.parity.acquire.cta.shared::cta.b64 p, [%1], %2;\n\t" \
        "selp.b32 %0, 1, 0, p;\n\t}" \
        : "=r"(_done) : "r"(_mbar), "r"(_parity) : "memory"); \
    if (!_done) { \
        asm volatile( \
            "{\n\t.reg .pred P1;\n\t" \
            "WAIT_LOOP_%=:\n\t" \
            "mbarrier.try_wait.parity.acquire.cta.shared::cta.b64 P1, [%0], %1, 0x989680;\n\t" \
            "@P1 bra.uni WAIT_DONE_%=;\n\t" \
            "bra.uni WAIT_LOOP_%=;\n\t" \
            "WAIT_DONE_%=:\n\t}" \
            :: "r"(_mbar), "r"(_parity) : "memory"); \
    } \
} while(0)

__device__ __forceinline__ void ldsm4(uint32_t* r, uint32_t addr) {
    asm volatile("ldmatrix.sync.aligned.m8n8.x4.shared.b16 {%0,%1,%2,%3}, [%4];"
        : "=r"(r[0]), "=r"(r[1]), "=r"(r[2]), "=r"(r[3]) : "r"(addr));
}
__device__ __forceinline__ void mma16816(float* d, const uint32_t* a, const uint32_t* b) {
    asm volatile(
        "mma.sync.aligned.m16n8k16.row.col.f32.f16.f16.f32 "
        "{%0,%1,%2,%3}, {%4,%5,%6,%7}, {%8,%9}, {%0,%1,%2,%3};"
        : "+f"(d[0]), "+f"(d[1]), "+f"(d[2]), "+f"(d[3])
        : "r"(a[0]), "r"(a[1]), "r"(a[2]), "r"(a[3]), "r"(b[0]), "r"(b[1]));
}
__device__ __forceinline__ uint32_t swz128(uint32_t o) {   // SW128 XOR swizzle
    return o ^ ((o >> 3) & 0x70);
}

// ================= convert / transpose kernels =================
__global__ void convert_x_kernel(const float* __restrict__ src)   // -> g_A1h
{
    int i = blockIdx.x * 256 + threadIdx.x;
    float4 v = ((const float4*)src)[i];
    __half2 p0 = __floats2half2_rn(v.x, v.y);
    __half2 p1 = __floats2half2_rn(v.z, v.w);
    uint2 ph = make_uint2(*(uint32_t*)&p0, *(uint32_t*)&p1);
    *(uint2*)&g_A1h[(size_t)i*4] = ph;
}

// generic: src [KD][ND] row-major -> dst [ND][KD] fp16
template<int ND, int KD>
__global__ void transpose_convert_kernel(const float* __restrict__ src, __half* __restrict__ dst)
{
    __shared__ float t[32][33];
    int n0 = blockIdx.x * 32, k0 = blockIdx.y * 32;
    int tx = threadIdx.x, ty = threadIdx.y;
#pragma unroll
    for (int i = 0; i < 4; i++)
        t[ty + i*8][tx] = src[(size_t)(k0 + ty + i*8) * ND + n0 + tx];
    __syncthreads();
#pragma unroll
    for (int i = 0; i < 4; i++) {
        int n = n0 + ty + i*8, k = k0 + tx;
        dst[(size_t)n * KD + k] = __float2half_rn(t[tx][ty + i*8]);
    }
}

// ================= main GEMM: TMA tensor loads (SW128), k-chunk 64, 3-stage ring =================
static constexpr uint32_t TILE16K = 128u * 128u;       // 16384 B per tile (128 rows x 128B)
static constexpr uint32_t STG = 2u * TILE16K;          // A + B per stage
static constexpr uint32_t GSMEM_B = 2048u + 3u * STG;  // 100352 B
static constexpr uint32_t TXB = 2u * TILE16K;          // 32768 bytes expected per stage

template<int WHICH>
__global__ __launch_bounds__(256, 2)
void mma_gemm_kernel(const __grid_constant__ CUtensorMap tmA,
                     const __grid_constant__ CUtensorMap tmB,
                     float* __restrict__ Cout)
{
    constexpr int KTOT = (WHICH == 1) ? DM : DI;
    constexpr int NC = KTOT / 64;

    extern __shared__ __align__(16) char smem[];
    uint32_t sb = smem_to_u32(smem);
    uint32_t tiles = (sb + 1024u + 1023u) & ~1023u;    // 1024-aligned tile region

    int tid = threadIdx.x;
    int lane = tid & 31, wid = tid >> 5;
    int wm = wid & 3, wn = wid >> 2;
    int m0 = blockIdx.y * 128;
    int n0 = blockIdx.x * 128;

    if (tid == 0) {
        MBARRIER_INIT(sb + 0, 1);
        MBARRIER_INIT(sb + 8, 1);
        MBARRIER_INIT(sb + 16, 1);
    }
    __syncthreads();

    auto issue = [&](int kc) {
        int st = kc % 3;
        uint32_t mb = sb + 8u * st;
        uint32_t base = tiles + st * STG;
        if (tid == 0) {
            MBARRIER_EXPECT_TX(mb, TXB);
            TMA_LOAD_2D(base,           &tmA, kc * 64, m0, mb);
            TMA_LOAD_2D(base + TILE16K, &tmB, kc * 64, n0, mb);
        }
    };

    issue(0); issue(1); issue(2);

    float d[2][8][4];
#pragma unroll
    for (int mt = 0; mt < 2; mt++)
#pragma unroll
        for (int nt = 0; nt < 8; nt++)
#pragma unroll
            for (int i = 0; i < 4; i++) d[mt][nt][i] = 0.f;

    int quad = lane >> 3, lrow = lane & 7;

    for (int kc = 0; kc < NC; kc++) {
        int st = kc % 3;
        MBARRIER_WAIT_PARITY(sb + 8u * st, (kc / 3) & 1);
        uint32_t bA = tiles + st * STG;
        uint32_t bB = bA + TILE16K;
#pragma unroll
        for (int ks = 0; ks < 4; ks++) {
            uint32_t aH[2][4];
#pragma unroll
            for (int mt = 0; mt < 2; mt++) {
                int row = wm * 32 + mt * 16 + (quad & 1) * 8 + lrow;
                uint32_t lin = (uint32_t)(row * 128) + (uint32_t)(ks * 32 + (quad >> 1) * 16);
                ldsm4(aH[mt], bA + swz128(lin));
            }
            uint32_t bH[8][2];
#pragma unroll
            for (int np = 0; np < 4; np++) {
                int nrow = wn * 64 + np * 16 + (quad >> 1) * 8 + lrow;
                uint32_t lin = (uint32_t)(nrow * 128) + (uint32_t)(ks * 32 + (quad & 1) * 16);
                uint32_t t[4];
                ldsm4(t, bB + swz128(lin));
                bH[np*2][0] = t[0]; bH[np*2][1] = t[1];
                bH[np*2+1][0] = t[2]; bH[np*2+1][1] = t[3];
            }
#pragma unroll
            for (int mt = 0; mt < 2; mt++)
#pragma unroll
                for (int nt = 0; nt < 8; nt++)
                    mma16816(d[mt][nt], aH[mt], bH[nt]);
        }
        __syncthreads();
        if (kc + 3 < NC) issue(kc + 3);
    }

    if (WHICH == 1) {
        // split epilogue: x-branch (n < DI) -> fp32 g_xf32; z-branch -> fp16 g_zh
        bool isx = (n0 < DI);
#pragma unroll
        for (int mt = 0; mt < 2; mt++)
#pragma unroll
            for (int nt = 0; nt < 8; nt++) {
                int row = m0 + wm * 32 + mt * 16 + (lane >> 2);
                int col = n0 + wn * 64 + nt * 8 + (lane & 3) * 2;
                if (isx) {
                    float2 v0 = {d[mt][nt][0], d[mt][nt][1]};
                    float2 v1 = {d[mt][nt][2], d[mt][nt][3]};
                    *(float2*)&g_xf32[(size_t)row * DI + col] = v0;
                    *(float2*)&g_xf32[(size_t)(row + 8) * DI + col] = v1;
                } else {
                    int zc = col - DI;
                    __half2 h0 = __floats2half2_rn(d[mt][nt][0], d[mt][nt][1]);
                    __half2 h1 = __floats2half2_rn(d[mt][nt][2], d[mt][nt][3]);
                    *(__half2*)&g_zh[(size_t)row * DI + zc] = h0;
                    *(__half2*)&g_zh[(size_t)(row + 8) * DI + zc] = h1;
                }
            }
    } else {
#pragma unroll
        for (int mt = 0; mt < 2; mt++)
#pragma unroll
            for (int nt = 0; nt < 8; nt++) {
                int row = m0 + wm * 32 + mt * 16 + (lane >> 2);
                int col = n0 + wn * 64 + nt * 8 + (lane & 3) * 2;
                float2 v0 = {d[mt][nt][0], d[mt][nt][1]};
                float2 v1 = {d[mt][nt][2], d[mt][nt][3]};
                *(float2*)&Cout[(size_t)row * DM + col] = v0;
                *(float2*)&Cout[(size_t)(row + 8) * DM + col] = v1;
            }
    }
}

// ---------------- conv: float4 sliding window, 4 ch/thread, fp16 output only ----------------
// grid (SS/16, DI/512, BB), block 128
__global__ __launch_bounds__(128)
void conv_kernel(const float* __restrict__ Wconv, const float* __restrict__ bconv)
{
    int tid = threadIdx.x;
    int b  = blockIdx.z;
    int c  = blockIdx.y * 512 + tid * 4;      // channel quad base
    int s0 = blockIdx.x * 16;

    float4 w0 = ((const float4*)Wconv)[c + 0];
    float4 w1 = ((const float4*)Wconv)[c + 1];
    float4 w2 = ((const float4*)Wconv)[c + 2];
    float4 w3 = ((const float4*)Wconv)[c + 3];
    float4 bs = *(const float4*)&bconv[c];

    const float* xin = g_xf32 + (size_t)b * SS * DI + c;
    __half* hout = g_xbch + (size_t)b * SS * DI + c;

    float4 xm3, xm2, xm1;
    float4 z4 = {0.f, 0.f, 0.f, 0.f};
    xm3 = (s0 >= 3) ? *(const float4*)&xin[(size_t)(s0 - 3) * DI] : z4;
    xm2 = (s0 >= 2) ? *(const float4*)&xin[(size_t)(s0 - 2) * DI] : z4;
    xm1 = (s0 >= 1) ? *(const float4*)&xin[(size_t)(s0 - 1) * DI] : z4;

#pragma unroll 4
    for (int r = 0; r < 16; r++) {
        float4 x0 = *(const float4*)&xin[(size_t)(s0 + r) * DI];
        float4 o;
        o.x = bs.x + w0.x * xm3.x + w0.y * xm2.x + w0.z * xm1.x + w0.w * x0.x;
        o.y = bs.y + w1.x * xm3.y + w1.y * xm2.y + w1.z * xm1.y + w1.w * x0.y;
        o.z = bs.z + w2.x * xm3.z + w2.y * xm2.z + w2.z * xm1.z + w2.w * x0.z;
        o.w = bs.w + w3.x * xm3.w + w3.y * xm2.w + w3.z * xm1.w + w3.w * x0.w;
        o.x = o.x / (1.f + __expf(-o.x));
        o.y = o.y / (1.f + __expf(-o.y));
        o.z = o.z / (1.f + __expf(-o.z));
        o.w = o.w / (1.f + __expf(-o.w));
        __half2 h0 = __floats2half2_rn(o.x, o.y);
        __half2 h1 = __floats2half2_rn(o.z, o.w);
        uint2 hp = make_uint2(*(uint32_t*)&h0, *(uint32_t*)&h1);
        *(uint2*)&hout[(size_t)(s0 + r) * DI] = hp;
        xm3 = xm2; xm2 = xm1; xm1 = x0;
    }
}

// ---------------- params mma: g_params[m][96] = xbc @ Wx ; also fp16 delta_in copy ----------------
static constexpr int PTS = 72;
__global__ __launch_bounds__(128)
void params_mma_kernel()
{
    __shared__ __align__(16) char ps[2 * (64 + 96) * PTS * 2];
    const uint32_t ST = (64 + 96) * PTS * 2;
    const uint32_t OB = 64 * PTS * 2;
    uint32_t sb = smem_to_u32(ps);

    int tid = threadIdx.x;
    int lane = tid & 31, wid = tid >> 5;
    int wm = wid & 1, wn = wid >> 1;
    int m0 = blockIdx.x * 64;

    float d[2][6][4];
#pragma unroll
    for (int mt = 0; mt < 2; mt++)
#pragma unroll
        for (int nt = 0; nt < 6; nt++)
#pragma unroll
            for (int i = 0; i < 4; i++) d[mt][nt][i] = 0.f;

    auto load_stage = [&](int stg, int kb) {
        uint32_t base = sb + stg * ST;
#pragma unroll
        for (int it = 0; it < 4; it++) {
            int u = tid + it * 128;
            int r = u >> 3, c8 = u & 7;
            CP_ASYNC16(base + (uint32_t)(r * PTS + c8 * 8) * 2,
                       g_xbch + (size_t)(m0 + r) * DI + kb + c8 * 8);
        }
#pragma unroll
        for (int it = 0; it < 6; it++) {
            int u = tid + it * 128;
            int r = u >> 3, c8 = u & 7;
            CP_ASYNC16(base + OB + (uint32_t)(r * PTS + c8 * 8) * 2,
                       g_Wxh + (size_t)r * DI + kb + c8 * 8);
        }
        CP_COMMIT();
    };

    load_stage(0, 0);
    int quad = lane >> 3, lrow = lane & 7;
    const int NC = DI / 64;

    for (int kc = 0; kc < NC; kc++) {
        if (kc + 1 < NC) { load_stage((kc + 1) & 1, (kc + 1) * 64); CP_WAIT(1); }
        else CP_WAIT(0);
        __syncthreads();
        uint32_t base = sb + (kc & 1) * ST;
#pragma unroll
        for (int ks = 0; ks < 4; ks++) {
            int k16 = ks * 16;
            uint32_t aH[2][4];
#pragma unroll
            for (int mt = 0; mt < 2; mt++) {
                int row = wm * 32 + mt * 16 + (quad & 1) * 8 + lrow;
                ldsm4(aH[mt], base + (uint32_t)(row * PTS + k16 + (quad >> 1) * 8) * 2);
            }
            uint32_t bH[6][2];
#pragma unroll
            for (int np = 0; np < 3; np++) {
                int nrow = wn * 48 + np * 16 + (quad >> 1) * 8 + lrow;
                uint32_t t[4];
                ldsm4(t, base + OB + (uint32_t)(nrow * PTS + k16 + (quad & 1) * 8) * 2);
                bH[np*2][0] = t[0]; bH[np*2][1] = t[1];
                bH[np*2+1][0] = t[2]; bH[np*2+1][1] = t[3];
            }
#pragma unroll
            for (int mt = 0; mt < 2; mt++)
#pragma unroll
                for (int nt = 0; nt < 6; nt++)
                    mma16816(d[mt][nt], aH[mt], bH[nt]);
        }
        __syncthreads();
    }

#pragma unroll
    for (int mt = 0; mt < 2; mt++)
#pragma unroll
        for (int nt = 0; nt < 6; nt++) {
            int row = m0 + wm * 32 + mt * 16 + (lane >> 2);
            int col = wn * 48 + nt * 8 + (lane & 3) * 2;
            float2 v0 = {d[mt][nt][0], d[mt][nt][1]};
            float2 v1 = {d[mt][nt][2], d[mt][nt][3]};
            *(float2*)&g_params[(size_t)row * 96 + col] = v0;
            *(float2*)&g_params[(size_t)(row + 8) * 96 + col] = v1;
            if (col < 64) {
                __half2 h0 = __floats2half2_rn(v0.x, v0.y);
                __half2 h1 = __floats2half2_rn(v1.x, v1.y);
                *(__half2*)&g_dinh[(size_t)row * 64 + col] = h0;
                *(__half2*)&g_dinh[(size_t)(row + 8) * 64 + col] = h1;
            }
        }
}

// ---------------- delta mma: g_delta[m][d] = softplus(delta_in @ Wdt + bdt) ----------------
__global__ __launch_bounds__(256)
void delta_mma_kernel(const float* __restrict__ bdt)
{
    __shared__ __align__(16) char ds[2 * 128 * PTS * 2];
    const uint32_t OB = 128 * PTS * 2;
    uint32_t sb = smem_to_u32(ds);

    int tid = threadIdx.x;
    int lane = tid & 31, wid = tid >> 5;
    int wm = wid & 3, wn = wid >> 2;
    int n0 = blockIdx.x * 128;
    int m0 = blockIdx.y * 128;

#pragma unroll
    for (int it = 0; it < 4; it++) {
        int u = tid + it * 256;
        int r = u >> 3, c8 = u & 7;
        CP_ASYNC16(sb + (uint32_t)(r * PTS + c8 * 8) * 2,
                   g_dinh + (size_t)(m0 + r) * 64 + c8 * 8);
    }
#pragma unroll
    for (int it = 0; it < 4; it++) {
        int u = tid + it * 256;
        int r = u >> 3, c8 = u & 7;
        CP_ASYNC16(sb + OB + (uint32_t)(r * PTS + c8 * 8) * 2,
                   g_Wdth + (size_t)(n0 + r) * 64 + c8 * 8);
    }
    CP_COMMIT();

    float d[2][8][4];
#pragma unroll
    for (int mt = 0; mt < 2; mt++)
#pragma unroll
        for (int nt = 0; nt < 8; nt++)
#pragma unroll
            for (int i = 0; i < 4; i++) d[mt][nt][i] = 0.f;

    CP_WAIT(0);
    __syncthreads();

    int quad = lane >> 3, lrow = lane & 7;
#pragma unroll
    for (int ks = 0; ks < 4; ks++) {
        int k16 = ks * 16;
        uint32_t aH[2][4];
#pragma unroll
        for (int mt = 0; mt < 2; mt++) {
            int row = wm * 32 + mt * 16 + (quad & 1) * 8 + lrow;
            ldsm4(aH[mt], sb + (uint32_t)(row * PTS + k16 + (quad >> 1) * 8) * 2);
        }
        uint32_t bH[8][2];
#pragma unroll
        for (int np = 0; np < 4; np++) {
            int nrow = wn * 64 + np * 16 + (quad >> 1) * 8 + lrow;
            uint32_t t[4];
            ldsm4(t, sb + OB + (uint32_t)(nrow * PTS + k16 + (quad & 1) * 8) * 2);
            bH[np*2][0] = t[0]; bH[np*2][1] = t[1];
            bH[np*2+1][0] = t[2]; bH[np*2+1][1] = t[3];
        }
#pragma unroll
        for (int mt = 0; mt < 2; mt++)
#pragma unroll
            for (int nt = 0; nt < 8; nt++)
                mma16816(d[mt][nt], aH[mt], bH[nt]);
    }

#pragma unroll
    for (int mt = 0; mt < 2; mt++)
#pragma unroll
        for (int nt = 0; nt < 8; nt++) {
            int row = m0 + wm * 32 + mt * 16 + (lane >> 2);
            int col = n0 + wn * 64 + nt * 8 + (lane & 3) * 2;
            float b0 = bdt[col], b1 = bdt[col + 1];
#pragma unroll
            for (int h = 0; h < 2; h++) {
                float t0 = d[mt][nt][h*2+0] + b0;
                float t1 = d[mt][nt][h*2+1] + b1;
                float2 v;
                v.x = fmaxf(t0, 0.f) + log1pf(__expf(-fabsf(t0)));
                v.y = fmaxf(t1, 0.f) + log1pf(__expf(-fabsf(t1)));
                *(float2*)&g_delta[(size_t)(row + h*8) * DI + col] = v;
            }
        }
}

// ---------------- selective scan + fused gating: writes g_A3h = y * silu(z) ----------------
__global__ __launch_bounds__(128, 8)
void scan_kernel(const float* __restrict__ A_log, const float* __restrict__ Dp)
{
    __shared__ float2 sh_duu[32][16];
    __shared__ float  sh_bc[32][32];
    __shared__ float  sh_y[32][16];
    int tid = threadIdx.x;
    int lane = tid & 31, w = tid >> 5;
    int gch0 = blockIdx.x * 16;
    int b  = gch0 / DI;
    int d0 = gch0 % DI;
    int q  = lane & 7;
    int ch = w * 4 + (lane >> 3);
    int d  = d0 + ch;

    float an0, an1;
    {
        float2 al = *(const float2*)&A_log[(size_t)d * DSTATE + 2 * q];
        an0 = -__expf(al.x) * 1.44269504f;
        an1 = -__expf(al.y) * 1.44269504f;
    }
    float dpv = Dp[d];
    float s0 = 0.f, s1 = 0.f;

    const float*  dmb = g_delta + (size_t)b * SS * DI + d0;
    const __half* umb = g_xbch + (size_t)b * SS * DI + d0;
    const __half* zmb = g_zh   + (size_t)b * SS * DI + d0;
    const float*  pmb = g_params + (size_t)b * SS * 96 + 64;
    __half* amb = g_A3h + (size_t)b * SS * DI + d0;

    for (int t0 = 0; t0 < SS; t0 += 32) {
#pragma unroll
        for (int k = 0; k < 4; k++) {
            int idx = tid + k * 128;
            int i = idx >> 4, j = idx & 15;
            size_t off = (size_t)(t0 + i) * DI + j;
            sh_duu[i][j] = make_float2(dmb[off], __half2float(umb[off]));
        }
#pragma unroll
        for (int k = 0; k < 8; k++) {
            int idx = tid + k * 128;
            int i = idx >> 5, j = idx & 31;
            sh_bc[i][j] = pmb[(size_t)(t0 + i) * 96 + j];
        }
        __syncthreads();

#pragma unroll 4
        for (int i = 0; i < 32; i++) {
            float2 duu = sh_duu[i][ch];
            float2 bq = *(float2*)&sh_bc[i][2 * q];
            float2 cq = *(float2*)&sh_bc[i][16 + 2 * q];
            float du = duu.x * duu.y;
            float e0 = exp2f(duu.x * an0);
            float e1 = exp2f(duu.x * an1);
            s0 = fmaf(e0, s0, du * bq.x);
            s1 = fmaf(e1, s1, du * bq.y);
            float acc = fmaf(s1, cq.y, s0 * cq.x);
            acc += __shfl_xor_sync(0xffffffffu, acc, 1);
            acc += __shfl_xor_sync(0xffffffffu, acc, 2);
            acc += __shfl_xor_sync(0xffffffffu, acc, 4);
            if (q == 0) sh_y[i][ch] = fmaf(duu.y, dpv, acc);
        }
        __syncthreads();
#pragma unroll
        for (int k = 0; k < 2; k++) {
            int idx = tid + k * 128;
            int i = idx >> 3, j = idx & 7;      // j: half2 index (2 channels)
            size_t off = (size_t)(t0 + i) * DI + 2 * j;
            __half2 zp = *(const __half2*)&zmb[off];
            float2 z = __half22float2(zp);
            float y0 = sh_y[i][2*j], y1 = sh_y[i][2*j + 1];
            float a0 = y0 * z.x / (1.f + __expf(-z.x));
            float a1 = y1 * z.y / (1.f + __expf(-z.y));
            *(__half2*)&amb[off] = __floats2half2_rn(a0, a1);
        }
    }
}

// ---------------- host: tensor-map plumbing ----------------
typedef CUresult (*EncodeFn)(CUtensorMap*, CUtensorMapDataType, cuuint32_t, void*,
                             const cuuint64_t*, const cuuint64_t*, const cuuint32_t*,
                             const cuuint32_t*, CUtensorMapInterleave, CUtensorMapSwizzle,
                             CUtensorMapL2promotion, CUtensorMapFloatOOBfill);

static EncodeFn get_encode_fn()
{
    static EncodeFn fn = nullptr;
    if (!fn) {
        void* p = nullptr;
        cudaDriverEntryPointQueryResult qr;
        cudaGetDriverEntryPointByVersion("cuTensorMapEncodeTiled", &p, 12000,
                                         cudaEnableDefault, &qr);
        fn = (EncodeFn)p;
    }
    return fn;
}

static void make_tm(CUtensorMap* tm, void* gaddr, uint64_t kdim, uint64_t rows)
{
    cuuint64_t dims[2]    = {kdim, rows};
    cuuint64_t strides[1] = {kdim * 2};
    cuuint32_t box[2]     = {64, 128};
    cuuint32_t es[2]      = {1, 1};
    get_encode_fn()(tm, CU_TENSOR_MAP_DATA_TYPE_FLOAT16, 2, gaddr,
                    dims, strides, box, es,
                    CU_TENSOR_MAP_INTERLEAVE_NONE, CU_TENSOR_MAP_SWIZZLE_128B,
                    CU_TENSOR_MAP_L2_PROMOTION_L2_128B,
                    CU_TENSOR_MAP_FLOAT_OOB_FILL_NONE);
}

// ---------------- launch ----------------
extern "C" void kernel_launch(void* const* d_in, const int* in_sizes, int n_in,
                              void* d_out, int out_size)
{
    (void)in_sizes; (void)n_in; (void)out_size;
    const float* x     = (const float*)d_in[0];
    const float* Win   = (const float*)d_in[1];
    const float* Wconv = (const float*)d_in[2];
    const float* bconv = (const float*)d_in[3];
    const float* Wx    = (const float*)d_in[4];
    const float* Wdt   = (const float*)d_in[5];
    const float* bdt   = (const float*)d_in[6];
    const float* A_log = (const float*)d_in[7];
    const float* Dp    = (const float*)d_in[8];
    const float* Wout  = (const float*)d_in[9];
    float* out = (float*)d_out;

    void *pA1h, *pB1h, *pA3h, *pB3h, *pWxh, *pWdth;
    cudaGetSymbolAddress(&pA1h, g_A1h);
    cudaGetSymbolAddress(&pB1h, g_B1h);
    cudaGetSymbolAddress(&pA3h, g_A3h);
    cudaGetSymbolAddress(&pB3h, g_B3h);
    cudaGetSymbolAddress(&pWxh, g_Wxh);
    cudaGetSymbolAddress(&pWdth, g_Wdth);

    CUtensorMap tmA1, tmB1, tmA3, tmB3;
    make_tm(&tmA1, pA1h, DM, MM);
    make_tm(&tmB1, pB1h, DM, 2*DI);
    make_tm(&tmA3, pA3h, DI, MM);
    make_tm(&tmB3, pB3h, DI, DM);

    cudaFuncSetAttribute(mma_gemm_kernel<1>, cudaFuncAttributeMaxDynamicSharedMemorySize, GSMEM_B);
    cudaFuncSetAttribute(mma_gemm_kernel<3>, cudaFuncAttributeMaxDynamicSharedMemorySize, GSMEM_B);

    convert_x_kernel<<<4096, 256>>>(x);
    transpose_convert_kernel<4096, 1024><<<dim3(128, 32), dim3(32, 8)>>>(Win, (__half*)pB1h);
    mma_gemm_kernel<1><<<dim3(32, 32), 256, GSMEM_B>>>(tmA1, tmB1, nullptr);  // x->g_xf32, z->g_zh
    conv_kernel<<<dim3(SS / 16, DI / 512, BB), 128>>>(Wconv, bconv);
    transpose_convert_kernel<96, 2048><<<dim3(3, 64), dim3(32, 8)>>>(Wx, (__half*)pWxh);
    params_mma_kernel<<<64, 128>>>();
    transpose_convert_kernel<2048, 64><<<dim3(64, 2), dim3(32, 8)>>>(Wdt, (__half*)pWdth);
    delta_mma_kernel<<<dim3(16, 32), 256>>>(bdt);
    scan_kernel<<<256, 128>>>(A_log, Dp);     // fused gating -> g_A3h
    transpose_convert_kernel<1024, 2048><<<dim3(32, 64), dim3(32, 8)>>>(Wout, (__half*)pB3h);
    mma_gemm_kernel<3><<<dim3(8, 32), 256, GSMEM_B>>>(tmA3, tmB3, out);       // out = A3@Wout
}

// round 11
// speedup vs baseline: 1.1781x; 1.1781x over previous
#include <cuda_runtime.h>
#include <cuda.h>
#include <cuda_fp16.h>
#include <math.h>
#include <stdint.h>

#define BB 2
#define SS 2048
#define DM 1024
#define DI 2048
#define DSTATE 16
#define RANK 64
#define MM (BB*SS)   /* 4096 rows (b,s) */

// ---------------- scratch (static device globals; no runtime allocation) ----------------
__device__ float  g_xf32[(size_t)MM * DI];      // GEMM1 x-branch, [m][d] fp32
__device__ __half g_zh[(size_t)MM * DI];        // GEMM1 z-branch, [m][d] fp16
__device__ __half g_xbch[(size_t)MM * DI];      // conv+silu (u), [m][d] fp16
__device__ float  g_params[(size_t)MM * 96];    // [m][96]  (delta_in | b | c)
__device__ __half g_dinh[(size_t)MM * RANK];    // fp16 delta_in for delta mma
__device__ float  g_delta[(size_t)MM * DI];     // softplus delta, [m][d]
__device__ __half g_yh[(size_t)MM * DI];        // scan output, [m][d] fp16

// fp16 operands for tensor-core GEMMs
__device__ __half g_A1h[(size_t)MM * DM];
__device__ __half g_B1h[(size_t)(2*DI) * DM];   // Win^T [N=4096][K=1024]
__device__ __half g_A3h[(size_t)MM * DI];       // gated y [4096][2048]
__device__ __half g_B3h[(size_t)DM * DI];       // Wout^T [N=1024][K=2048]
__device__ __half g_Wxh[(size_t)96 * DI];       // Wx^T  [96][2048]
__device__ __half g_Wdth[(size_t)DI * RANK];    // Wdt^T [2048][64]

// ================= low-level helpers =================
__device__ __forceinline__ uint32_t smem_to_u32(const void* smem_ptr) {
    uint32_t addr;
    asm("{ .reg .u64 tmp; cvta.to.shared.u64 tmp, %1; cvt.u32.u64 %0, tmp; }"
        : "=r"(addr) : "l"(smem_ptr));
    return addr;
}
#define CP_ASYNC16(saddr, gaddr) \
    asm volatile("cp.async.cg.shared.global [%0], [%1], 16;" :: "r"(saddr), "l"(gaddr))
#define CP_COMMIT() asm volatile("cp.async.commit_group;" ::: "memory")
#define CP_WAIT(n)  asm volatile("cp.async.wait_group %0;" :: "n"(n) : "memory")

#define MBARRIER_INIT(mbar, count) \
    asm volatile("mbarrier.init.shared.b64 [%0], %1;" \
        :: "r"((uint32_t)(mbar)), "r"((uint32_t)(count)) : "memory")
#define MBARRIER_EXPECT_TX(mbar, tx) \
    asm volatile("mbarrier.arrive.expect_tx.shared.b64 _, [%0], %1;" \
        :: "r"((uint32_t)(mbar)), "r"((uint32_t)(tx)) : "memory")
#define TMA_LOAD_2D(dst, tmap, x, y, mbar) \
    asm volatile("cp.async.bulk.tensor.2d.shared::cta.global.tile.mbarrier::complete_tx::bytes " \
        "[%0], [%1, {%2, %3}], [%4];" \
        :: "r"((uint32_t)(dst)), "l"(tmap), "r"((int)(x)), "r"((int)(y)), "r"((uint32_t)(mbar)) : "memory")

#define MBARRIER_WAIT_PARITY(mbar_smem_addr, phase_parity) do { \
    uint32_t _mbar = (uint32_t)(mbar_smem_addr); \
    uint32_t _parity = (uint32_t)(phase_parity); \
    uint32_t _done; \
    asm volatile( \
        "{\n\t.reg .pred p;\n\t" \
        "mbarrier.try_wait.parity.acquire.cta.shared::cta.b64 p, [%1], %2;\n\t" \
        "selp.b32 %0, 1, 0, p;\n\t}" \
        : "=r"(_done) : "r"(_mbar), "r"(_parity) : "memory"); \
    if (!_done) { \
        asm volatile( \
            "{\n\t.reg .pred P1;\n\t" \
            "WAIT_LOOP_%=:\n\t" \
            "mbarrier.try_wait.parity.acquire.cta.shared::cta.b64 P1, [%0], %1, 0x989680;\n\t" \
            "@P1 bra.uni WAIT_DONE_%=;\n\t" \
            "bra.uni WAIT_LOOP_%=;\n\t" \
            "WAIT_DONE_%=:\n\t}" \
            :: "r"(_mbar), "r"(_parity) : "memory"); \
    } \
} while(0)

__device__ __forceinline__ void ldsm4(uint32_t* r, uint32_t addr) {
    asm volatile("ldmatrix.sync.aligned.m8n8.x4.shared.b16 {%0,%1,%2,%3}, [%4];"
        : "=r"(r[0]), "=r"(r[1]), "=r"(r[2]), "=r"(r[3]) : "r"(addr));
}
__device__ __forceinline__ void mma16816(float* d, const uint32_t* a, const uint32_t* b) {
    asm volatile(
        "mma.sync.aligned.m16n8k16.row.col.f32.f16.f16.f32 "
        "{%0,%1,%2,%3}, {%4,%5,%6,%7}, {%8,%9}, {%0,%1,%2,%3};"
        : "+f"(d[0]), "+f"(d[1]), "+f"(d[2]), "+f"(d[3])
        : "r"(a[0]), "r"(a[1]), "r"(a[2]), "r"(a[3]), "r"(b[0]), "r"(b[1]));
}
__device__ __forceinline__ uint32_t swz128(uint32_t o) {   // SW128 XOR swizzle
    return o ^ ((o >> 3) & 0x70);
}

// ================= convert / transpose kernels =================
__global__ void convert_x_kernel(const float* __restrict__ src)   // -> g_A1h
{
    int i = blockIdx.x * 256 + threadIdx.x;
    float4 v = ((const float4*)src)[i];
    __half2 p0 = __floats2half2_rn(v.x, v.y);
    __half2 p1 = __floats2half2_rn(v.z, v.w);
    uint2 ph = make_uint2(*(uint32_t*)&p0, *(uint32_t*)&p1);
    *(uint2*)&g_A1h[(size_t)i*4] = ph;
}

__global__ void gate_convert_kernel()   // A3 = y * silu(z), fp16 in/out
{
    int i = blockIdx.x * 256 + threadIdx.x;   // 2M quads
    size_t e = (size_t)i * 4;
    uint2 yp = *(const uint2*)&g_yh[e];
    uint2 zp = *(const uint2*)&g_zh[e];
    float2 y0 = __half22float2(*(__half2*)&yp.x);
    float2 y1 = __half22float2(*(__half2*)&yp.y);
    float2 z0 = __half22float2(*(__half2*)&zp.x);
    float2 z1 = __half22float2(*(__half2*)&zp.y);
    float a0 = y0.x * z0.x / (1.f + __expf(-z0.x));
    float a1 = y0.y * z0.y / (1.f + __expf(-z0.y));
    float a2 = y1.x * z1.x / (1.f + __expf(-z1.x));
    float a3 = y1.y * z1.y / (1.f + __expf(-z1.y));
    __half2 p0 = __floats2half2_rn(a0, a1);
    __half2 p1 = __floats2half2_rn(a2, a3);
    uint2 ph = make_uint2(*(uint32_t*)&p0, *(uint32_t*)&p1);
    *(uint2*)&g_A3h[e] = ph;
}

// generic: src [KD][ND] row-major -> dst [ND][KD] fp16
template<int ND, int KD>
__global__ void transpose_convert_kernel(const float* __restrict__ src, __half* __restrict__ dst)
{
    __shared__ float t[32][33];
    int n0 = blockIdx.x * 32, k0 = blockIdx.y * 32;
    int tx = threadIdx.x, ty = threadIdx.y;
#pragma unroll
    for (int i = 0; i < 4; i++)
        t[ty + i*8][tx] = src[(size_t)(k0 + ty + i*8) * ND + n0 + tx];
    __syncthreads();
#pragma unroll
    for (int i = 0; i < 4; i++) {
        int n = n0 + ty + i*8, k = k0 + tx;
        dst[(size_t)n * KD + k] = __float2half_rn(t[tx][ty + i*8]);
    }
}

// ================= main GEMM: TMA tensor loads (SW128), k-chunk 64, 3-stage ring =================
static constexpr uint32_t TILE16K = 128u * 128u;       // 16384 B per tile (128 rows x 128B)
static constexpr uint32_t STG = 2u * TILE16K;          // A + B per stage
static constexpr uint32_t GSMEM_B = 2048u + 3u * STG;  // 100352 B
static constexpr uint32_t TXB = 2u * TILE16K;          // 32768 bytes expected per stage

template<int WHICH>
__global__ __launch_bounds__(256, 2)
void mma_gemm_kernel(const __grid_constant__ CUtensorMap tmA,
                     const __grid_constant__ CUtensorMap tmB,
                     float* __restrict__ Cout)
{
    constexpr int KTOT = (WHICH == 1) ? DM : DI;
    constexpr int NC = KTOT / 64;

    extern __shared__ __align__(16) char smem[];
    uint32_t sb = smem_to_u32(smem);
    uint32_t tiles = (sb + 1024u + 1023u) & ~1023u;    // 1024-aligned tile region

    int tid = threadIdx.x;
    int lane = tid & 31, wid = tid >> 5;
    int wm = wid & 3, wn = wid >> 2;
    int m0 = blockIdx.y * 128;
    int n0 = blockIdx.x * 128;

    if (tid == 0) {
        MBARRIER_INIT(sb + 0, 1);
        MBARRIER_INIT(sb + 8, 1);
        MBARRIER_INIT(sb + 16, 1);
    }
    __syncthreads();

    auto issue = [&](int kc) {
        int st = kc % 3;
        uint32_t mb = sb + 8u * st;
        uint32_t base = tiles + st * STG;
        if (tid == 0) {
            MBARRIER_EXPECT_TX(mb, TXB);
            TMA_LOAD_2D(base,           &tmA, kc * 64, m0, mb);
            TMA_LOAD_2D(base + TILE16K, &tmB, kc * 64, n0, mb);
        }
    };

    issue(0); issue(1); issue(2);

    float d[2][8][4];
#pragma unroll
    for (int mt = 0; mt < 2; mt++)
#pragma unroll
        for (int nt = 0; nt < 8; nt++)
#pragma unroll
            for (int i = 0; i < 4; i++) d[mt][nt][i] = 0.f;

    int quad = lane >> 3, lrow = lane & 7;

    for (int kc = 0; kc < NC; kc++) {
        int st = kc % 3;
        MBARRIER_WAIT_PARITY(sb + 8u * st, (kc / 3) & 1);
        uint32_t bA = tiles + st * STG;
        uint32_t bB = bA + TILE16K;
#pragma unroll
        for (int ks = 0; ks < 4; ks++) {
            uint32_t aH[2][4];
#pragma unroll
            for (int mt = 0; mt < 2; mt++) {
                int row = wm * 32 + mt * 16 + (quad & 1) * 8 + lrow;
                uint32_t lin = (uint32_t)(row * 128) + (uint32_t)(ks * 32 + (quad >> 1) * 16);
                ldsm4(aH[mt], bA + swz128(lin));
            }
            uint32_t bH[8][2];
#pragma unroll
            for (int np = 0; np < 4; np++) {
                int nrow = wn * 64 + np * 16 + (quad >> 1) * 8 + lrow;
                uint32_t lin = (uint32_t)(nrow * 128) + (uint32_t)(ks * 32 + (quad & 1) * 16);
                uint32_t t[4];
                ldsm4(t, bB + swz128(lin));
                bH[np*2][0] = t[0]; bH[np*2][1] = t[1];
                bH[np*2+1][0] = t[2]; bH[np*2+1][1] = t[3];
            }
#pragma unroll
            for (int mt = 0; mt < 2; mt++)
#pragma unroll
                for (int nt = 0; nt < 8; nt++)
                    mma16816(d[mt][nt], aH[mt], bH[nt]);
        }
        __syncthreads();
        if (kc + 3 < NC) issue(kc + 3);
    }

    if (WHICH == 1) {
        // split epilogue: x-branch (n < DI) -> fp32 g_xf32; z-branch -> fp16 g_zh
        bool isx = (n0 < DI);
#pragma unroll
        for (int mt = 0; mt < 2; mt++)
#pragma unroll
            for (int nt = 0; nt < 8; nt++) {
                int row = m0 + wm * 32 + mt * 16 + (lane >> 2);
                int col = n0 + wn * 64 + nt * 8 + (lane & 3) * 2;
                if (isx) {
                    float2 v0 = {d[mt][nt][0], d[mt][nt][1]};
                    float2 v1 = {d[mt][nt][2], d[mt][nt][3]};
                    *(float2*)&g_xf32[(size_t)row * DI + col] = v0;
                    *(float2*)&g_xf32[(size_t)(row + 8) * DI + col] = v1;
                } else {
                    int zc = col - DI;
                    __half2 h0 = __floats2half2_rn(d[mt][nt][0], d[mt][nt][1]);
                    __half2 h1 = __floats2half2_rn(d[mt][nt][2], d[mt][nt][3]);
                    *(__half2*)&g_zh[(size_t)row * DI + zc] = h0;
                    *(__half2*)&g_zh[(size_t)(row + 8) * DI + zc] = h1;
                }
            }
    } else {
#pragma unroll
        for (int mt = 0; mt < 2; mt++)
#pragma unroll
            for (int nt = 0; nt < 8; nt++) {
                int row = m0 + wm * 32 + mt * 16 + (lane >> 2);
                int col = n0 + wn * 64 + nt * 8 + (lane & 3) * 2;
                float2 v0 = {d[mt][nt][0], d[mt][nt][1]};
                float2 v1 = {d[mt][nt][2], d[mt][nt][3]};
                *(float2*)&Cout[(size_t)row * DM + col] = v0;
                *(float2*)&Cout[(size_t)(row + 8) * DM + col] = v1;
            }
    }
}

// ---------------- conv: float4 sliding window, 4 ch/thread, fp16 output only ----------------
// grid (SS/16, DI/512, BB), block 128
__global__ __launch_bounds__(128)
void conv_kernel(const float* __restrict__ Wconv, const float* __restrict__ bconv)
{
    int tid = threadIdx.x;
    int b  = blockIdx.z;
    int c  = blockIdx.y * 512 + tid * 4;      // channel quad base
    int s0 = blockIdx.x * 16;

    float4 w0 = ((const float4*)Wconv)[c + 0];
    float4 w1 = ((const float4*)Wconv)[c + 1];
    float4 w2 = ((const float4*)Wconv)[c + 2];
    float4 w3 = ((const float4*)Wconv)[c + 3];
    float4 bs = *(const float4*)&bconv[c];

    const float* xin = g_xf32 + (size_t)b * SS * DI + c;
    __half* hout = g_xbch + (size_t)b * SS * DI + c;

    float4 xm3, xm2, xm1;
    float4 z4 = {0.f, 0.f, 0.f, 0.f};
    xm3 = (s0 >= 3) ? *(const float4*)&xin[(size_t)(s0 - 3) * DI] : z4;
    xm2 = (s0 >= 2) ? *(const float4*)&xin[(size_t)(s0 - 2) * DI] : z4;
    xm1 = (s0 >= 1) ? *(const float4*)&xin[(size_t)(s0 - 1) * DI] : z4;

#pragma unroll 4
    for (int r = 0; r < 16; r++) {
        float4 x0 = *(const float4*)&xin[(size_t)(s0 + r) * DI];
        float4 o;
        o.x = bs.x + w0.x * xm3.x + w0.y * xm2.x + w0.z * xm1.x + w0.w * x0.x;
        o.y = bs.y + w1.x * xm3.y + w1.y * xm2.y + w1.z * xm1.y + w1.w * x0.y;
        o.z = bs.z + w2.x * xm3.z + w2.y * xm2.z + w2.z * xm1.z + w2.w * x0.z;
        o.w = bs.w + w3.x * xm3.w + w3.y * xm2.w + w3.z * xm1.w + w3.w * x0.w;
        o.x = o.x / (1.f + __expf(-o.x));
        o.y = o.y / (1.f + __expf(-o.y));
        o.z = o.z / (1.f + __expf(-o.z));
        o.w = o.w / (1.f + __expf(-o.w));
        __half2 h0 = __floats2half2_rn(o.x, o.y);
        __half2 h1 = __floats2half2_rn(o.z, o.w);
        uint2 hp = make_uint2(*(uint32_t*)&h0, *(uint32_t*)&h1);
        *(uint2*)&hout[(size_t)(s0 + r) * DI] = hp;
        xm3 = xm2; xm2 = xm1; xm1 = x0;
    }
}

// ---------------- params mma: g_params[m][96] = xbc @ Wx ; also fp16 delta_in copy ----------------
static constexpr int PTS = 72;
__global__ __launch_bounds__(128)
void params_mma_kernel()
{
    __shared__ __align__(16) char ps[2 * (64 + 96) * PTS * 2];
    const uint32_t ST = (64 + 96) * PTS * 2;
    const uint32_t OB = 64 * PTS * 2;
    uint32_t sb = smem_to_u32(ps);

    int tid = threadIdx.x;
    int lane = tid & 31, wid = tid >> 5;
    int wm = wid & 1, wn = wid >> 1;
    int m0 = blockIdx.x * 64;

    float d[2][6][4];
#pragma unroll
    for (int mt = 0; mt < 2; mt++)
#pragma unroll
        for (int nt = 0; nt < 6; nt++)
#pragma unroll
            for (int i = 0; i < 4; i++) d[mt][nt][i] = 0.f;

    auto load_stage = [&](int stg, int kb) {
        uint32_t base = sb + stg * ST;
#pragma unroll
        for (int it = 0; it < 4; it++) {
            int u = tid + it * 128;
            int r = u >> 3, c8 = u & 7;
            CP_ASYNC16(base + (uint32_t)(r * PTS + c8 * 8) * 2,
                       g_xbch + (size_t)(m0 + r) * DI + kb + c8 * 8);
        }
#pragma unroll
        for (int it = 0; it < 6; it++) {
            int u = tid + it * 128;
            int r = u >> 3, c8 = u & 7;
            CP_ASYNC16(base + OB + (uint32_t)(r * PTS + c8 * 8) * 2,
                       g_Wxh + (size_t)r * DI + kb + c8 * 8);
        }
        CP_COMMIT();
    };

    load_stage(0, 0);
    int quad = lane >> 3, lrow = lane & 7;
    const int NC = DI / 64;

    for (int kc = 0; kc < NC; kc++) {
        if (kc + 1 < NC) { load_stage((kc + 1) & 1, (kc + 1) * 64); CP_WAIT(1); }
        else CP_WAIT(0);
        __syncthreads();
        uint32_t base = sb + (kc & 1) * ST;
#pragma unroll
        for (int ks = 0; ks < 4; ks++) {
            int k16 = ks * 16;
            uint32_t aH[2][4];
#pragma unroll
            for (int mt = 0; mt < 2; mt++) {
                int row = wm * 32 + mt * 16 + (quad & 1) * 8 + lrow;
                ldsm4(aH[mt], base + (uint32_t)(row * PTS + k16 + (quad >> 1) * 8) * 2);
            }
            uint32_t bH[6][2];
#pragma unroll
            for (int np = 0; np < 3; np++) {
                int nrow = wn * 48 + np * 16 + (quad >> 1) * 8 + lrow;
                uint32_t t[4];
                ldsm4(t, base + OB + (uint32_t)(nrow * PTS + k16 + (quad & 1) * 8) * 2);
                bH[np*2][0] = t[0]; bH[np*2][1] = t[1];
                bH[np*2+1][0] = t[2]; bH[np*2+1][1] = t[3];
            }
#pragma unroll
            for (int mt = 0; mt < 2; mt++)
#pragma unroll
                for (int nt = 0; nt < 6; nt++)
                    mma16816(d[mt][nt], aH[mt], bH[nt]);
        }
        __syncthreads();
    }

#pragma unroll
    for (int mt = 0; mt < 2; mt++)
#pragma unroll
        for (int nt = 0; nt < 6; nt++) {
            int row = m0 + wm * 32 + mt * 16 + (lane >> 2);
            int col = wn * 48 + nt * 8 + (lane & 3) * 2;
            float2 v0 = {d[mt][nt][0], d[mt][nt][1]};
            float2 v1 = {d[mt][nt][2], d[mt][nt][3]};
            *(float2*)&g_params[(size_t)row * 96 + col] = v0;
            *(float2*)&g_params[(size_t)(row + 8) * 96 + col] = v1;
            if (col < 64) {
                __half2 h0 = __floats2half2_rn(v0.x, v0.y);
                __half2 h1 = __floats2half2_rn(v1.x, v1.y);
                *(__half2*)&g_dinh[(size_t)row * 64 + col] = h0;
                *(__half2*)&g_dinh[(size_t)(row + 8) * 64 + col] = h1;
            }
        }
}

// ---------------- delta mma: g_delta[m][d] = softplus(delta_in @ Wdt + bdt) ----------------
__global__ __launch_bounds__(256)
void delta_mma_kernel(const float* __restrict__ bdt)
{
    __shared__ __align__(16) char ds[2 * 128 * PTS * 2];
    const uint32_t OB = 128 * PTS * 2;
    uint32_t sb = smem_to_u32(ds);

    int tid = threadIdx.x;
    int lane = tid & 31, wid = tid >> 5;
    int wm = wid & 3, wn = wid >> 2;
    int n0 = blockIdx.x * 128;
    int m0 = blockIdx.y * 128;

#pragma unroll
    for (int it = 0; it < 4; it++) {
        int u = tid + it * 256;
        int r = u >> 3, c8 = u & 7;
        CP_ASYNC16(sb + (uint32_t)(r * PTS + c8 * 8) * 2,
                   g_dinh + (size_t)(m0 + r) * 64 + c8 * 8);
    }
#pragma unroll
    for (int it = 0; it < 4; it++) {
        int u = tid + it * 256;
        int r = u >> 3, c8 = u & 7;
        CP_ASYNC16(sb + OB + (uint32_t)(r * PTS + c8 * 8) * 2,
                   g_Wdth + (size_t)(n0 + r) * 64 + c8 * 8);
    }
    CP_COMMIT();

    float d[2][8][4];
#pragma unroll
    for (int mt = 0; mt < 2; mt++)
#pragma unroll
        for (int nt = 0; nt < 8; nt++)
#pragma unroll
            for (int i = 0; i < 4; i++) d[mt][nt][i] = 0.f;

    CP_WAIT(0);
    __syncthreads();

    int quad = lane >> 3, lrow = lane & 7;
#pragma unroll
    for (int ks = 0; ks < 4; ks++) {
        int k16 = ks * 16;
        uint32_t aH[2][4];
#pragma unroll
        for (int mt = 0; mt < 2; mt++) {
            int row = wm * 32 + mt * 16 + (quad & 1) * 8 + lrow;
            ldsm4(aH[mt], sb + (uint32_t)(row * PTS + k16 + (quad >> 1) * 8) * 2);
        }
        uint32_t bH[8][2];
#pragma unroll
        for (int np = 0; np < 4; np++) {
            int nrow = wn * 64 + np * 16 + (quad >> 1) * 8 + lrow;
            uint32_t t[4];
            ldsm4(t, sb + OB + (uint32_t)(nrow * PTS + k16 + (quad & 1) * 8) * 2);
            bH[np*2][0] = t[0]; bH[np*2][1] = t[1];
            bH[np*2+1][0] = t[2]; bH[np*2+1][1] = t[3];
        }
#pragma unroll
        for (int mt = 0; mt < 2; mt++)
#pragma unroll
            for (int nt = 0; nt < 8; nt++)
                mma16816(d[mt][nt], aH[mt], bH[nt]);
    }

#pragma unroll
    for (int mt = 0; mt < 2; mt++)
#pragma unroll
        for (int nt = 0; nt < 8; nt++) {
            int row = m0 + wm * 32 + mt * 16 + (lane >> 2);
            int col = n0 + wn * 64 + nt * 8 + (lane & 3) * 2;
            float b0 = bdt[col], b1 = bdt[col + 1];
#pragma unroll
            for (int h = 0; h < 2; h++) {
                float t0 = d[mt][nt][h*2+0] + b0;
                float t1 = d[mt][nt][h*2+1] + b1;
                float2 v;
                v.x = fmaxf(t0, 0.f) + log1pf(__expf(-fabsf(t0)));
                v.y = fmaxf(t1, 0.f) + log1pf(__expf(-fabsf(t1)));
                *(float2*)&g_delta[(size_t)(row + h*8) * DI + col] = v;
            }
        }
}

// ---------------- selective scan: 8 lanes/channel, 2 states/lane; u fp16 in, y fp16 out ----------------
__global__ __launch_bounds__(128, 8)
void scan_kernel(const float* __restrict__ A_log, const float* __restrict__ Dp)
{
    __shared__ float2 sh_duu[32][16];
    __shared__ float  sh_bc[32][32];
    __shared__ float  sh_y[32][16];
    int tid = threadIdx.x;
    int lane = tid & 31, w = tid >> 5;
    int gch0 = blockIdx.x * 16;
    int b  = gch0 / DI;
    int d0 = gch0 % DI;
    int q  = lane & 7;
    int ch = w * 4 + (lane >> 3);
    int d  = d0 + ch;

    float an0, an1;
    {
        float2 al = *(const float2*)&A_log[(size_t)d * DSTATE + 2 * q];
        an0 = -__expf(al.x) * 1.44269504f;
        an1 = -__expf(al.y) * 1.44269504f;
    }
    float dpv = Dp[d];
    float s0 = 0.f, s1 = 0.f;

    const float*  dmb = g_delta + (size_t)b * SS * DI + d0;
    const __half* umb = g_xbch + (size_t)b * SS * DI + d0;
    const float*  pmb = g_params + (size_t)b * SS * 96 + 64;
    __half* ymb = g_yh + (size_t)b * SS * DI + d0;

    for (int t0 = 0; t0 < SS; t0 += 32) {
#pragma unroll
        for (int k = 0; k < 4; k++) {
            int idx = tid + k * 128;
            int i = idx >> 4, j = idx & 15;
            size_t off = (size_t)(t0 + i) * DI + j;
            sh_duu[i][j] = make_float2(dmb[off], __half2float(umb[off]));
        }
#pragma unroll
        for (int k = 0; k < 8; k++) {
            int idx = tid + k * 128;
            int i = idx >> 5, j = idx & 31;
            sh_bc[i][j] = pmb[(size_t)(t0 + i) * 96 + j];
        }
        __syncthreads();

#pragma unroll 4
        for (int i = 0; i < 32; i++) {
            float2 duu = sh_duu[i][ch];
            float2 bq = *(float2*)&sh_bc[i][2 * q];
            float2 cq = *(float2*)&sh_bc[i][16 + 2 * q];
            float du = duu.x * duu.y;
            float e0 = exp2f(duu.x * an0);
            float e1 = exp2f(duu.x * an1);
            s0 = fmaf(e0, s0, du * bq.x);
            s1 = fmaf(e1, s1, du * bq.y);
            float acc = fmaf(s1, cq.y, s0 * cq.x);
            acc += __shfl_xor_sync(0xffffffffu, acc, 1);
            acc += __shfl_xor_sync(0xffffffffu, acc, 2);
            acc += __shfl_xor_sync(0xffffffffu, acc, 4);
            if (q == 0) sh_y[i][ch] = fmaf(duu.y, dpv, acc);
        }
        __syncthreads();
#pragma unroll
        for (int k = 0; k < 2; k++) {
            int idx = tid + k * 128;
            int i = idx >> 3, j = idx & 7;      // j: half2 index (2 channels)
            __half2 hv = __floats2half2_rn(sh_y[i][2*j], sh_y[i][2*j + 1]);
            *(__half2*)&ymb[(size_t)(t0 + i) * DI + 2*j] = hv;
        }
    }
}

// ---------------- host: tensor-map plumbing ----------------
typedef CUresult (*EncodeFn)(CUtensorMap*, CUtensorMapDataType, cuuint32_t, void*,
                             const cuuint64_t*, const cuuint64_t*, const cuuint32_t*,
                             const cuuint32_t*, CUtensorMapInterleave, CUtensorMapSwizzle,
                             CUtensorMapL2promotion, CUtensorMapFloatOOBfill);

static EncodeFn get_encode_fn()
{
    static EncodeFn fn = nullptr;
    if (!fn) {
        void* p = nullptr;
        cudaDriverEntryPointQueryResult qr;
        cudaGetDriverEntryPointByVersion("cuTensorMapEncodeTiled", &p, 12000,
                                         cudaEnableDefault, &qr);
        fn = (EncodeFn)p;
    }
    return fn;
}

static void make_tm(CUtensorMap* tm, void* gaddr, uint64_t kdim, uint64_t rows)
{
    cuuint64_t dims[2]    = {kdim, rows};
    cuuint64_t strides[1] = {kdim * 2};
    cuuint32_t box[2]     = {64, 128};
    cuuint32_t es[2]      = {1, 1};
    get_encode_fn()(tm, CU_TENSOR_MAP_DATA_TYPE_FLOAT16, 2, gaddr,
                    dims, strides, box, es,
                    CU_TENSOR_MAP_INTERLEAVE_NONE, CU_TENSOR_MAP_SWIZZLE_128B,
                    CU_TENSOR_MAP_L2_PROMOTION_L2_128B,
                    CU_TENSOR_MAP_FLOAT_OOB_FILL_NONE);
}

// ---------------- launch ----------------
extern "C" void kernel_launch(void* const* d_in, const int* in_sizes, int n_in,
                              void* d_out, int out_size)
{
    (void)in_sizes; (void)n_in; (void)out_size;
    const float* x     = (const float*)d_in[0];
    const float* Win   = (const float*)d_in[1];
    const float* Wconv = (const float*)d_in[2];
    const float* bconv = (const float*)d_in[3];
    const float* Wx    = (const float*)d_in[4];
    const float* Wdt   = (const float*)d_in[5];
    const float* bdt   = (const float*)d_in[6];
    const float* A_log = (const float*)d_in[7];
    const float* Dp    = (const float*)d_in[8];
    const float* Wout  = (const float*)d_in[9];
    float* out = (float*)d_out;

    void *pA1h, *pB1h, *pA3h, *pB3h, *pWxh, *pWdth;
    cudaGetSymbolAddress(&pA1h, g_A1h);
    cudaGetSymbolAddress(&pB1h, g_B1h);
    cudaGetSymbolAddress(&pA3h, g_A3h);
    cudaGetSymbolAddress(&pB3h, g_B3h);
    cudaGetSymbolAddress(&pWxh, g_Wxh);
    cudaGetSymbolAddress(&pWdth, g_Wdth);

    CUtensorMap tmA1, tmB1, tmA3, tmB3;
    make_tm(&tmA1, pA1h, DM, MM);
    make_tm(&tmB1, pB1h, DM, 2*DI);
    make_tm(&tmA3, pA3h, DI, MM);
    make_tm(&tmB3, pB3h, DI, DM);

    cudaFuncSetAttribute(mma_gemm_kernel<1>, cudaFuncAttributeMaxDynamicSharedMemorySize, GSMEM_B);
    cudaFuncSetAttribute(mma_gemm_kernel<3>, cudaFuncAttributeMaxDynamicSharedMemorySize, GSMEM_B);

    convert_x_kernel<<<4096, 256>>>(x);
    transpose_convert_kernel<4096, 1024><<<dim3(128, 32), dim3(32, 8)>>>(Win, (__half*)pB1h);
    mma_gemm_kernel<1><<<dim3(32, 32), 256, GSMEM_B>>>(tmA1, tmB1, nullptr);  // x->g_xf32, z->g_zh
    conv_kernel<<<dim3(SS / 16, DI / 512, BB), 128>>>(Wconv, bconv);
    transpose_convert_kernel<96, 2048><<<dim3(3, 64), dim3(32, 8)>>>(Wx, (__half*)pWxh);
    params_mma_kernel<<<64, 128>>>();
    transpose_convert_kernel<2048, 64><<<dim3(64, 2), dim3(32, 8)>>>(Wdt, (__half*)pWdth);
    delta_mma_kernel<<<dim3(16, 32), 256>>>(bdt);
    scan_kernel<<<256, 128>>>(A_log, Dp);
    gate_convert_kernel<<<8192, 256>>>();
    transpose_convert_kernel<1024, 2048><<<dim3(32, 64), dim3(32, 8)>>>(Wout, (__half*)pB3h);
    mma_gemm_kernel<3><<<dim3(8, 32), 256, GSMEM_B>>>(tmA3, tmB3, out);       // out = A3@Wout
}

// round 13
// speedup vs baseline: 1.1853x; 1.0061x over previous
#include <cuda_runtime.h>
#include <cuda.h>
#include <cuda_fp16.h>
#include <math.h>
#include <stdint.h>

#define BB 2
#define SS 2048
#define DM 1024
#define DI 2048
#define DSTATE 16
#define RANK 64
#define MM (BB*SS)   /* 4096 rows (b,s) */

// ---------------- scratch (static device globals; no runtime allocation) ----------------
__device__ float  g_xf32[(size_t)MM * DI];      // GEMM1 x-branch, [m][d] fp32
__device__ __half g_zh[(size_t)MM * DI];        // GEMM1 z-branch, [m][d] fp16
__device__ __half g_xbch[(size_t)MM * DI];      // conv+silu (u), [m][d] fp16
__device__ float  g_params[(size_t)MM * 96];    // [m][96]  (delta_in | b | c)
__device__ __half g_dinh[(size_t)MM * RANK];    // fp16 delta_in for delta mma
__device__ float  g_delta[(size_t)MM * DI];     // softplus delta, [m][d]
__device__ __half g_yh[(size_t)MM * DI];        // scan output, [m][d] fp16

// fp16 operands for tensor-core GEMMs
__device__ __half g_A1h[(size_t)MM * DM];
__device__ __half g_B1h[(size_t)(2*DI) * DM];   // Win^T [N=4096][K=1024]
__device__ __half g_A3h[(size_t)MM * DI];       // gated y [4096][2048]
__device__ __half g_B3h[(size_t)DM * DI];       // Wout^T [N=1024][K=2048]
__device__ __half g_Wxh[(size_t)96 * DI];       // Wx^T  [96][2048]
__device__ __half g_Wdth[(size_t)DI * RANK];    // Wdt^T [2048][64]

// prep_kernel block budget (MUST sum to PREP_BLOCKS)
static constexpr int PB_CONV  = 4096;                       // convert_x
static constexpr int PB_WIN   = (2*DI/32) * (DM/32);        // 128*32 = 4096
static constexpr int PB_WOUT  = (DM/32) * (DI/32);          // 32*64  = 2048
static constexpr int PB_WX    = (96/32) * (DI/32);          // 3*64   = 192
static constexpr int PB_WDT   = (DI/32) * (RANK/32);        // 64*2   = 128
static constexpr int PREP_BLOCKS = PB_CONV + PB_WIN + PB_WOUT + PB_WX + PB_WDT;  // 10560

// ================= low-level helpers =================
__device__ __forceinline__ uint32_t smem_to_u32(const void* smem_ptr) {
    uint32_t addr;
    asm("{ .reg .u64 tmp; cvta.to.shared.u64 tmp, %1; cvt.u32.u64 %0, tmp; }"
        : "=r"(addr) : "l"(smem_ptr));
    return addr;
}
#define CP_ASYNC16(saddr, gaddr) \
    asm volatile("cp.async.cg.shared.global [%0], [%1], 16;" :: "r"(saddr), "l"(gaddr))
#define CP_COMMIT() asm volatile("cp.async.commit_group;" ::: "memory")
#define CP_WAIT(n)  asm volatile("cp.async.wait_group %0;" :: "n"(n) : "memory")

#define MBARRIER_INIT(mbar, count) \
    asm volatile("mbarrier.init.shared.b64 [%0], %1;" \
        :: "r"((uint32_t)(mbar)), "r"((uint32_t)(count)) : "memory")
#define MBARRIER_EXPECT_TX(mbar, tx) \
    asm volatile("mbarrier.arrive.expect_tx.shared.b64 _, [%0], %1;" \
        :: "r"((uint32_t)(mbar)), "r"((uint32_t)(tx)) : "memory")
#define TMA_LOAD_2D(dst, tmap, x, y, mbar) \
    asm volatile("cp.async.bulk.tensor.2d.shared::cta.global.tile.mbarrier::complete_tx::bytes " \
        "[%0], [%1, {%2, %3}], [%4];" \
        :: "r"((uint32_t)(dst)), "l"(tmap), "r"((int)(x)), "r"((int)(y)), "r"((uint32_t)(mbar)) : "memory")

#define MBARRIER_WAIT_PARITY(mbar_smem_addr, phase_parity) do { \
    uint32_t _mbar = (uint32_t)(mbar_smem_addr); \
    uint32_t _parity = (uint32_t)(phase_parity); \
    uint32_t _done; \
    asm volatile( \
        "{\n\t.reg .pred p;\n\t" \
        "mbarrier.try_wait.parity.acquire.cta.shared::cta.b64 p, [%1], %2;\n\t" \
        "selp.b32 %0, 1, 0, p;\n\t}" \
        : "=r"(_done) : "r"(_mbar), "r"(_parity) : "memory"); \
    if (!_done) { \
        asm volatile( \
            "{\n\t.reg .pred P1;\n\t" \
            "WAIT_LOOP_%=:\n\t" \
            "mbarrier.try_wait.parity.acquire.cta.shared::cta.b64 P1, [%0], %1, 0x989680;\n\t" \
            "@P1 bra.uni WAIT_DONE_%=;\n\t" \
            "bra.uni WAIT_LOOP_%=;\n\t" \
            "WAIT_DONE_%=:\n\t}" \
            :: "r"(_mbar), "r"(_parity) : "memory"); \
    } \
} while(0)

__device__ __forceinline__ void ldsm4(uint32_t* r, uint32_t addr) {
    asm volatile("ldmatrix.sync.aligned.m8n8.x4.shared.b16 {%0,%1,%2,%3}, [%4];"
        : "=r"(r[0]), "=r"(r[1]), "=r"(r[2]), "=r"(r[3]) : "r"(addr));
}
__device__ __forceinline__ void mma16816(float* d, const uint32_t* a, const uint32_t* b) {
    asm volatile(
        "mma.sync.aligned.m16n8k16.row.col.f32.f16.f16.f32 "
        "{%0,%1,%2,%3}, {%4,%5,%6,%7}, {%8,%9}, {%0,%1,%2,%3};"
        : "+f"(d[0]), "+f"(d[1]), "+f"(d[2]), "+f"(d[3])
        : "r"(a[0]), "r"(a[1]), "r"(a[2]), "r"(a[3]), "r"(b[0]), "r"(b[1]));
}
__device__ __forceinline__ uint32_t swz128(uint32_t o) {   // SW128 XOR swizzle
    return o ^ ((o >> 3) & 0x70);
}

// ================= fused prep: convert_x + 4 weight transposes, one launch =================
__device__ __forceinline__ void tile_transpose(const float* __restrict__ src,
                                               __half* __restrict__ dst,
                                               int ND, int KD, int n0, int k0,
                                               float (*t)[33], int tx, int ty)
{
#pragma unroll
    for (int i = 0; i < 4; i++)
        t[ty + i*8][tx] = src[(size_t)(k0 + ty + i*8) * ND + n0 + tx];
    __syncthreads();
#pragma unroll
    for (int i = 0; i < 4; i++) {
        int n = n0 + ty + i*8, k = k0 + tx;
        dst[(size_t)n * KD + k] = __float2half_rn(t[tx][ty + i*8]);
    }
}

// grid PREP_BLOCKS x 256 threads
__global__ void prep_kernel(const float* __restrict__ x,   const float* __restrict__ Win,
                            const float* __restrict__ Wx,  const float* __restrict__ Wdt,
                            const float* __restrict__ Wout)
{
    __shared__ float t[32][33];
    int tid = threadIdx.x;
    int tx = tid & 31, ty = tid >> 5;
    int bid = blockIdx.x;

    if (bid < PB_CONV) {                      // convert_x -> g_A1h
        int i = bid * 256 + tid;
        float4 v = ((const float4*)x)[i];
        __half2 p0 = __floats2half2_rn(v.x, v.y);
        __half2 p1 = __floats2half2_rn(v.z, v.w);
        uint2 ph = make_uint2(*(uint32_t*)&p0, *(uint32_t*)&p1);
        *(uint2*)&g_A1h[(size_t)i*4] = ph;
        return;
    }
    bid -= PB_CONV;
    if (bid < PB_WIN) {                       // Win [1024][4096] -> g_B1h [4096][1024]
        int bx = bid & 127, by = bid >> 7;
        tile_transpose(Win, g_B1h, 2*DI, DM, bx*32, by*32, t, tx, ty);
        return;
    }
    bid -= PB_WIN;
    if (bid < PB_WOUT) {                      // Wout [2048][1024] -> g_B3h [1024][2048]
        int bx = bid & 31, by = bid >> 5;
        tile_transpose(Wout, g_B3h, DM, DI, bx*32, by*32, t, tx, ty);
        return;
    }
    bid -= PB_WOUT;
    if (bid < PB_WX) {                        // Wx [2048][96] -> g_Wxh [96][2048]
        int bx = bid % 3, by = bid / 3;
        tile_transpose(Wx, g_Wxh, 96, DI, bx*32, by*32, t, tx, ty);
        return;
    }
    bid -= PB_WX;
    {                                         // Wdt [64][2048] -> g_Wdth [2048][64]
        int bx = bid & 63, by = bid >> 6;     // bx: 0..63 (n tiles), by: 0..1 (k tiles)
        tile_transpose(Wdt, g_Wdth, DI, RANK, bx*32, by*32, t, tx, ty);
    }
}

__global__ void gate_convert_kernel()   // A3 = y * silu(z), fp16 in/out
{
    int i = blockIdx.x * 256 + threadIdx.x;   // 2M quads
    size_t e = (size_t)i * 4;
    uint2 yp = *(const uint2*)&g_yh[e];
    uint2 zp = *(const uint2*)&g_zh[e];
    float2 y0 = __half22float2(*(__half2*)&yp.x);
    float2 y1 = __half22float2(*(__half2*)&yp.y);
    float2 z0 = __half22float2(*(__half2*)&zp.x);
    float2 z1 = __half22float2(*(__half2*)&zp.y);
    float a0 = y0.x * z0.x / (1.f + __expf(-z0.x));
    float a1 = y0.y * z0.y / (1.f + __expf(-z0.y));
    float a2 = y1.x * z1.x / (1.f + __expf(-z1.x));
    float a3 = y1.y * z1.y / (1.f + __expf(-z1.y));
    __half2 p0 = __floats2half2_rn(a0, a1);
    __half2 p1 = __floats2half2_rn(a2, a3);
    uint2 ph = make_uint2(*(uint32_t*)&p0, *(uint32_t*)&p1);
    *(uint2*)&g_A3h[e] = ph;
}

// ================= main GEMM: TMA tensor loads (SW128), k-chunk 64, 3-stage ring =================
static constexpr uint32_t TILE16K = 128u * 128u;
static constexpr uint32_t STG = 2u * TILE16K;
static constexpr uint32_t GSMEM_B = 2048u + 3u * STG;
static constexpr uint32_t TXB = 2u * TILE16K;

template<int WHICH>
__global__ __launch_bounds__(256, 2)
void mma_gemm_kernel(const __grid_constant__ CUtensorMap tmA,
                     const __grid_constant__ CUtensorMap tmB,
                     float* __restrict__ Cout)
{
    constexpr int KTOT = (WHICH == 1) ? DM : DI;
    constexpr int NC = KTOT / 64;

    extern __shared__ __align__(16) char smem[];
    uint32_t sb = smem_to_u32(smem);
    uint32_t tiles = (sb + 1024u + 1023u) & ~1023u;

    int tid = threadIdx.x;
    int lane = tid & 31, wid = tid >> 5;
    int wm = wid & 3, wn = wid >> 2;
    int m0 = blockIdx.y * 128;
    int n0 = blockIdx.x * 128;

    if (tid == 0) {
        MBARRIER_INIT(sb + 0, 1);
        MBARRIER_INIT(sb + 8, 1);
        MBARRIER_INIT(sb + 16, 1);
    }
    __syncthreads();

    auto issue = [&](int kc) {
        int st = kc % 3;
        uint32_t mb = sb + 8u * st;
        uint32_t base = tiles + st * STG;
        if (tid == 0) {
            MBARRIER_EXPECT_TX(mb, TXB);
            TMA_LOAD_2D(base,           &tmA, kc * 64, m0, mb);
            TMA_LOAD_2D(base + TILE16K, &tmB, kc * 64, n0, mb);
        }
    };

    issue(0); issue(1); issue(2);

    float d[2][8][4];
#pragma unroll
    for (int mt = 0; mt < 2; mt++)
#pragma unroll
        for (int nt = 0; nt < 8; nt++)
#pragma unroll
            for (int i = 0; i < 4; i++) d[mt][nt][i] = 0.f;

    int quad = lane >> 3, lrow = lane & 7;

    for (int kc = 0; kc < NC; kc++) {
        int st = kc % 3;
        MBARRIER_WAIT_PARITY(sb + 8u * st, (kc / 3) & 1);
        uint32_t bA = tiles + st * STG;
        uint32_t bB = bA + TILE16K;
#pragma unroll
        for (int ks = 0; ks < 4; ks++) {
            uint32_t aH[2][4];
#pragma unroll
            for (int mt = 0; mt < 2; mt++) {
                int row = wm * 32 + mt * 16 + (quad & 1) * 8 + lrow;
                uint32_t lin = (uint32_t)(row * 128) + (uint32_t)(ks * 32 + (quad >> 1) * 16);
                ldsm4(aH[mt], bA + swz128(lin));
            }
            uint32_t bH[8][2];
#pragma unroll
            for (int np = 0; np < 4; np++) {
                int nrow = wn * 64 + np * 16 + (quad >> 1) * 8 + lrow;
                uint32_t lin = (uint32_t)(nrow * 128) + (uint32_t)(ks * 32 + (quad & 1) * 16);
                uint32_t t[4];
                ldsm4(t, bB + swz128(lin));
                bH[np*2][0] = t[0]; bH[np*2][1] = t[1];
                bH[np*2+1][0] = t[2]; bH[np*2+1][1] = t[3];
            }
#pragma unroll
            for (int mt = 0; mt < 2; mt++)
#pragma unroll
                for (int nt = 0; nt < 8; nt++)
                    mma16816(d[mt][nt], aH[mt], bH[nt]);
        }
        __syncthreads();
        if (kc + 3 < NC) issue(kc + 3);
    }

    if (WHICH == 1) {
        bool isx = (n0 < DI);
#pragma unroll
        for (int mt = 0; mt < 2; mt++)
#pragma unroll
            for (int nt = 0; nt < 8; nt++) {
                int row = m0 + wm * 32 + mt * 16 + (lane >> 2);
                int col = n0 + wn * 64 + nt * 8 + (lane & 3) * 2;
                if (isx) {
                    float2 v0 = {d[mt][nt][0], d[mt][nt][1]};
                    float2 v1 = {d[mt][nt][2], d[mt][nt][3]};
                    *(float2*)&g_xf32[(size_t)row * DI + col] = v0;
                    *(float2*)&g_xf32[(size_t)(row + 8) * DI + col] = v1;
                } else {
                    int zc = col - DI;
                    __half2 h0 = __floats2half2_rn(d[mt][nt][0], d[mt][nt][1]);
                    __half2 h1 = __floats2half2_rn(d[mt][nt][2], d[mt][nt][3]);
                    *(__half2*)&g_zh[(size_t)row * DI + zc] = h0;
                    *(__half2*)&g_zh[(size_t)(row + 8) * DI + zc] = h1;
                }
            }
    } else {
#pragma unroll
        for (int mt = 0; mt < 2; mt++)
#pragma unroll
            for (int nt = 0; nt < 8; nt++) {
                int row = m0 + wm * 32 + mt * 16 + (lane >> 2);
                int col = n0 + wn * 64 + nt * 8 + (lane & 3) * 2;
                float2 v0 = {d[mt][nt][0], d[mt][nt][1]};
                float2 v1 = {d[mt][nt][2], d[mt][nt][3]};
                *(float2*)&Cout[(size_t)row * DM + col] = v0;
                *(float2*)&Cout[(size_t)(row + 8) * DM + col] = v1;
            }
    }
}

// ---------------- conv: float2 sliding window, 2 ch/thread, fp16 output only ----------------
// grid (SS/16, DI/256, BB), block 128
__global__ __launch_bounds__(128)
void conv_kernel(const float* __restrict__ Wconv, const float* __restrict__ bconv)
{
    int tid = threadIdx.x;
    int b  = blockIdx.z;
    int c  = blockIdx.y * 256 + tid * 2;      // channel pair base
    int s0 = blockIdx.x * 16;

    float4 w0 = ((const float4*)Wconv)[c + 0];
    float4 w1 = ((const float4*)Wconv)[c + 1];
    float2 bs = *(const float2*)&bconv[c];

    const float* xin = g_xf32 + (size_t)b * SS * DI + c;
    __half* hout = g_xbch + (size_t)b * SS * DI + c;

    float2 xm3, xm2, xm1;
    float2 z2 = {0.f, 0.f};
    xm3 = (s0 >= 3) ? *(const float2*)&xin[(size_t)(s0 - 3) * DI] : z2;
    xm2 = (s0 >= 2) ? *(const float2*)&xin[(size_t)(s0 - 2) * DI] : z2;
    xm1 = (s0 >= 1) ? *(const float2*)&xin[(size_t)(s0 - 1) * DI] : z2;

#pragma unroll 4
    for (int r = 0; r < 16; r++) {
        float2 x0 = *(const float2*)&xin[(size_t)(s0 + r) * DI];
        float2 o;
        o.x = bs.x + w0.x * xm3.x + w0.y * xm2.x + w0.z * xm1.x + w0.w * x0.x;
        o.y = bs.y + w1.x * xm3.y + w1.y * xm2.y + w1.z * xm1.y + w1.w * x0.y;
        o.x = o.x / (1.f + __expf(-o.x));
        o.y = o.y / (1.f + __expf(-o.y));
        __half2 h = __floats2half2_rn(o.x, o.y);
        *(__half2*)&hout[(size_t)(s0 + r) * DI] = h;
        xm3 = xm2; xm2 = xm1; xm1 = x0;
    }
}

// ---------------- params mma: 32-row tiles, 128 blocks ----------------
static constexpr int PTS = 72;
__global__ __launch_bounds__(128)
void params_mma_kernel()
{
    __shared__ __align__(16) char ps[2 * (32 + 96) * PTS * 2];
    const uint32_t ST = (32 + 96) * PTS * 2;
    const uint32_t OB = 32 * PTS * 2;
    uint32_t sb = smem_to_u32(ps);

    int tid = threadIdx.x;
    int lane = tid & 31, wid = tid >> 5;
    int wm = wid & 1, wn = wid >> 1;
    int m0 = blockIdx.x * 32;

    float d[6][4];
#pragma unroll
    for (int nt = 0; nt < 6; nt++)
#pragma unroll
        for (int i = 0; i < 4; i++) d[nt][i] = 0.f;

    auto load_stage = [&](int stg, int kb) {
        uint32_t base = sb + stg * ST;
#pragma unroll
        for (int it = 0; it < 2; it++) {          // A: 32 rows x 64k
            int u = tid + it * 128;
            int r = u >> 3, c8 = u & 7;
            CP_ASYNC16(base + (uint32_t)(r * PTS + c8 * 8) * 2,
                       g_xbch + (size_t)(m0 + r) * DI + kb + c8 * 8);
        }
#pragma unroll
        for (int it = 0; it < 6; it++) {          // B: 96 rows x 64k
            int u = tid + it * 128;
            int r = u >> 3, c8 = u & 7;
            CP_ASYNC16(base + OB + (uint32_t)(r * PTS + c8 * 8) * 2,
                       g_Wxh + (size_t)r * DI + kb + c8 * 8);
        }
        CP_COMMIT();
    };

    load_stage(0, 0);
    int quad = lane >> 3, lrow = lane & 7;
    const int NC = DI / 64;

    for (int kc = 0; kc < NC; kc++) {
        if (kc + 1 < NC) { load_stage((kc + 1) & 1, (kc + 1) * 64); CP_WAIT(1); }
        else CP_WAIT(0);
        __syncthreads();
        uint32_t base = sb + (kc & 1) * ST;
#pragma unroll
        for (int ks = 0; ks < 4; ks++) {
            int k16 = ks * 16;
            uint32_t aH[4];
            {
                int row = wm * 16 + (quad & 1) * 8 + lrow;
                ldsm4(aH, base + (uint32_t)(row * PTS + k16 + (quad >> 1) * 8) * 2);
            }
            uint32_t bH[6][2];
#pragma unroll
            for (int np = 0; np < 3; np++) {
                int nrow = wn * 48 + np * 16 + (quad >> 1) * 8 + lrow;
                uint32_t t[4];
                ldsm4(t, base + OB + (uint32_t)(nrow * PTS + k16 + (quad & 1) * 8) * 2);
                bH[np*2][0] = t[0]; bH[np*2][1] = t[1];
                bH[np*2+1][0] = t[2]; bH[np*2+1][1] = t[3];
            }
#pragma unroll
            for (int nt = 0; nt < 6; nt++)
                mma16816(d[nt], aH, bH[nt]);
        }
        __syncthreads();
    }

#pragma unroll
    for (int nt = 0; nt < 6; nt++) {
        int row = m0 + wm * 16 + (lane >> 2);
        int col = wn * 48 + nt * 8 + (lane & 3) * 2;
        float2 v0 = {d[nt][0], d[nt][1]};
        float2 v1 = {d[nt][2], d[nt][3]};
        *(float2*)&g_params[(size_t)row * 96 + col] = v0;
        *(float2*)&g_params[(size_t)(row + 8) * 96 + col] = v1;
        if (col < 64) {
            __half2 h0 = __floats2half2_rn(v0.x, v0.y);
            __half2 h1 = __floats2half2_rn(v1.x, v1.y);
            *(__half2*)&g_dinh[(size_t)row * 64 + col] = h0;
            *(__half2*)&g_dinh[(size_t)(row + 8) * 64 + col] = h1;
        }
    }
}

// ---------------- delta mma: g_delta[m][d] = softplus(delta_in @ Wdt + bdt) ----------------
__global__ __launch_bounds__(256)
void delta_mma_kernel(const float* __restrict__ bdt)
{
    __shared__ __align__(16) char ds[2 * 128 * PTS * 2];
    const uint32_t OB = 128 * PTS * 2;
    uint32_t sb = smem_to_u32(ds);

    int tid = threadIdx.x;
    int lane = tid & 31, wid = tid >> 5;
    int wm = wid & 3, wn = wid >> 2;
    int n0 = blockIdx.x * 128;
    int m0 = blockIdx.y * 128;

#pragma unroll
    for (int it = 0; it < 4; it++) {
        int u = tid + it * 256;
        int r = u >> 3, c8 = u & 7;
        CP_ASYNC16(sb + (uint32_t)(r * PTS + c8 * 8) * 2,
                   g_dinh + (size_t)(m0 + r) * 64 + c8 * 8);
    }
#pragma unroll
    for (int it = 0; it < 4; it++) {
        int u = tid + it * 256;
        int r = u >> 3, c8 = u & 7;
        CP_ASYNC16(sb + OB + (uint32_t)(r * PTS + c8 * 8) * 2,
                   g_Wdth + (size_t)(n0 + r) * 64 + c8 * 8);
    }
    CP_COMMIT();

    float d[2][8][4];
#pragma unroll
    for (int mt = 0; mt < 2; mt++)
#pragma unroll
        for (int nt = 0; nt < 8; nt++)
#pragma unroll
            for (int i = 0; i < 4; i++) d[mt][nt][i] = 0.f;

    CP_WAIT(0);
    __syncthreads();

    int quad = lane >> 3, lrow = lane & 7;
#pragma unroll
    for (int ks = 0; ks < 4; ks++) {
        int k16 = ks * 16;
        uint32_t aH[2][4];
#pragma unroll
        for (int mt = 0; mt < 2; mt++) {
            int row = wm * 32 + mt * 16 + (quad & 1) * 8 + lrow;
            ldsm4(aH[mt], sb + (uint32_t)(row * PTS + k16 + (quad >> 1) * 8) * 2);
        }
        uint32_t bH[8][2];
#pragma unroll
        for (int np = 0; np < 4; np++) {
            int nrow = wn * 64 + np * 16 + (quad >> 1) * 8 + lrow;
            uint32_t t[4];
            ldsm4(t, sb + OB + (uint32_t)(nrow * PTS + k16 + (quad & 1) * 8) * 2);
            bH[np*2][0] = t[0]; bH[np*2][1] = t[1];
            bH[np*2+1][0] = t[2]; bH[np*2+1][1] = t[3];
        }
#pragma unroll
        for (int mt = 0; mt < 2; mt++)
#pragma unroll
            for (int nt = 0; nt < 8; nt++)
                mma16816(d[mt][nt], aH[mt], bH[nt]);
    }

#pragma unroll
    for (int mt = 0; mt < 2; mt++)
#pragma unroll
        for (int nt = 0; nt < 8; nt++) {
            int row = m0 + wm * 32 + mt * 16 + (lane >> 2);
            int col = n0 + wn * 64 + nt * 8 + (lane & 3) * 2;
            float b0 = bdt[col], b1 = bdt[col + 1];
#pragma unroll
            for (int h = 0; h < 2; h++) {
                float t0 = d[mt][nt][h*2+0] + b0;
                float t1 = d[mt][nt][h*2+1] + b1;
                float2 v;
                v.x = fmaxf(t0, 0.f) + log1pf(__expf(-fabsf(t0)));
                v.y = fmaxf(t1, 0.f) + log1pf(__expf(-fabsf(t1)));
                *(float2*)&g_delta[(size_t)(row + h*8) * DI + col] = v;
            }
        }
}

// ---------------- selective scan: 8 lanes/channel, 2 states/lane; u fp16 in, y fp16 out ----------------
__global__ __launch_bounds__(128, 8)
void scan_kernel(const float* __restrict__ A_log, const float* __restrict__ Dp)
{
    __shared__ float2 sh_duu[32][16];
    __shared__ float  sh_bc[32][32];
    __shared__ float  sh_y[32][16];
    int tid = threadIdx.x;
    int lane = tid & 31, w = tid >> 5;
    int gch0 = blockIdx.x * 16;
    int b  = gch0 / DI;
    int d0 = gch0 % DI;
    int q  = lane & 7;
    int ch = w * 4 + (lane >> 3);
    int d  = d0 + ch;

    float an0, an1;
    {
        float2 al = *(const float2*)&A_log[(size_t)d * DSTATE + 2 * q];
        an0 = -__expf(al.x) * 1.44269504f;
        an1 = -__expf(al.y) * 1.44269504f;
    }
    float dpv = Dp[d];
    float s0 = 0.f, s1 = 0.f;

    const float*  dmb = g_delta + (size_t)b * SS * DI + d0;
    const __half* umb = g_xbch + (size_t)b * SS * DI + d0;
    const float*  pmb = g_params + (size_t)b * SS * 96 + 64;
    __half* ymb = g_yh + (size_t)b * SS * DI + d0;

    for (int t0 = 0; t0 < SS; t0 += 32) {
#pragma unroll
        for (int k = 0; k < 4; k++) {
            int idx = tid + k * 128;
            int i = idx >> 4, j = idx & 15;
            size_t off = (size_t)(t0 + i) * DI + j;
            sh_duu[i][j] = make_float2(dmb[off], __half2float(umb[off]));
        }
#pragma unroll
        for (int k = 0; k < 8; k++) {
            int idx = tid + k * 128;
            int i = idx >> 5, j = idx & 31;
            sh_bc[i][j] = pmb[(size_t)(t0 + i) * 96 + j];
        }
        __syncthreads();

#pragma unroll 4
        for (int i = 0; i < 32; i++) {
            float2 duu = sh_duu[i][ch];
            float2 bq = *(float2*)&sh_bc[i][2 * q];
            float2 cq = *(float2*)&sh_bc[i][16 + 2 * q];
            float du = duu.x * duu.y;
            float e0 = exp2f(duu.x * an0);
            float e1 = exp2f(duu.x * an1);
            s0 = fmaf(e0, s0, du * bq.x);
            s1 = fmaf(e1, s1, du * bq.y);
            float acc = fmaf(s1, cq.y, s0 * cq.x);
            acc += __shfl_xor_sync(0xffffffffu, acc, 1);
            acc += __shfl_xor_sync(0xffffffffu, acc, 2);
            acc += __shfl_xor_sync(0xffffffffu, acc, 4);
            if (q == 0) sh_y[i][ch] = fmaf(duu.y, dpv, acc);
        }
        __syncthreads();
#pragma unroll
        for (int k = 0; k < 2; k++) {
            int idx = tid + k * 128;
            int i = idx >> 3, j = idx & 7;
            __half2 hv = __floats2half2_rn(sh_y[i][2*j], sh_y[i][2*j + 1]);
            *(__half2*)&ymb[(size_t)(t0 + i) * DI + 2*j] = hv;
        }
    }
}

// ---------------- host: tensor-map plumbing ----------------
typedef CUresult (*EncodeFn)(CUtensorMap*, CUtensorMapDataType, cuuint32_t, void*,
                             const cuuint64_t*, const cuuint64_t*, const cuuint32_t*,
                             const cuuint32_t*, CUtensorMapInterleave, CUtensorMapSwizzle,
                             CUtensorMapL2promotion, CUtensorMapFloatOOBfill);

static EncodeFn get_encode_fn()
{
    static EncodeFn fn = nullptr;
    if (!fn) {
        void* p = nullptr;
        cudaDriverEntryPointQueryResult qr;
        cudaGetDriverEntryPointByVersion("cuTensorMapEncodeTiled", &p, 12000,
                                         cudaEnableDefault, &qr);
        fn = (EncodeFn)p;
    }
    return fn;
}

static void make_tm(CUtensorMap* tm, void* gaddr, uint64_t kdim, uint64_t rows)
{
    cuuint64_t dims[2]    = {kdim, rows};
    cuuint64_t strides[1] = {kdim * 2};
    cuuint32_t box[2]     = {64, 128};
    cuuint32_t es[2]      = {1, 1};
    get_encode_fn()(tm, CU_TENSOR_MAP_DATA_TYPE_FLOAT16, 2, gaddr,
                    dims, strides, box, es,
                    CU_TENSOR_MAP_INTERLEAVE_NONE, CU_TENSOR_MAP_SWIZZLE_128B,
                    CU_TENSOR_MAP_L2_PROMOTION_L2_128B,
                    CU_TENSOR_MAP_FLOAT_OOB_FILL_NONE);
}

// ---------------- launch ----------------
extern "C" void kernel_launch(void* const* d_in, const int* in_sizes, int n_in,
                              void* d_out, int out_size)
{
    (void)in_sizes; (void)n_in; (void)out_size;
    const float* x     = (const float*)d_in[0];
    const float* Win   = (const float*)d_in[1];
    const float* Wconv = (const float*)d_in[2];
    const float* bconv = (const float*)d_in[3];
    const float* Wx    = (const float*)d_in[4];
    const float* Wdt   = (const float*)d_in[5];
    const float* bdt   = (const float*)d_in[6];
    const float* A_log = (const float*)d_in[7];
    const float* Dp    = (const float*)d_in[8];
    const float* Wout  = (const float*)d_in[9];
    float* out = (float*)d_out;

    void *pA1h, *pB1h, *pA3h, *pB3h;
    cudaGetSymbolAddress(&pA1h, g_A1h);
    cudaGetSymbolAddress(&pB1h, g_B1h);
    cudaGetSymbolAddress(&pA3h, g_A3h);
    cudaGetSymbolAddress(&pB3h, g_B3h);

    CUtensorMap tmA1, tmB1, tmA3, tmB3;
    make_tm(&tmA1, pA1h, DM, MM);
    make_tm(&tmB1, pB1h, DM, 2*DI);
    make_tm(&tmA3, pA3h, DI, MM);
    make_tm(&tmB3, pB3h, DI, DM);

    cudaFuncSetAttribute(mma_gemm_kernel<1>, cudaFuncAttributeMaxDynamicSharedMemorySize, GSMEM_B);
    cudaFuncSetAttribute(mma_gemm_kernel<3>, cudaFuncAttributeMaxDynamicSharedMemorySize, GSMEM_B);

    prep_kernel<<<PREP_BLOCKS, 256>>>(x, Win, Wx, Wdt, Wout);               // all converts+transposes
    mma_gemm_kernel<1><<<dim3(32, 32), 256, GSMEM_B>>>(tmA1, tmB1, nullptr); // x->g_xf32, z->g_zh
    conv_kernel<<<dim3(SS / 16, DI / 256, BB), 128>>>(Wconv, bconv);
    params_mma_kernel<<<128, 128>>>();
    delta_mma_kernel<<<dim3(16, 32), 256>>>(bdt);
    scan_kernel<<<256, 128>>>(A_log, Dp);
    gate_convert_kernel<<<8192, 256>>>();
    mma_gemm_kernel<3><<<dim3(8, 32), 256, GSMEM_B>>>(tmA3, tmB3, out);      // out = A3@Wout
}

// round 14
// speedup vs baseline: 1.1996x; 1.0121x over previous
#include <cuda_runtime.h>
#include <cuda.h>
#include <cuda_fp16.h>
#include <math.h>
#include <stdint.h>

#define BB 2
#define SS 2048
#define DM 1024
#define DI 2048
#define DSTATE 16
#define RANK 64
#define MM (BB*SS)   /* 4096 rows (b,s) */

// ---------------- scratch (static device globals; no runtime allocation) ----------------
__device__ float  g_xf32[(size_t)MM * DI];      // GEMM1 x-branch, [m][d] fp32
__device__ __half g_zh[(size_t)MM * DI];        // GEMM1 z-branch, [m][d] fp16
__device__ __half g_xbch[(size_t)MM * DI];      // conv+silu (u), [m][d] fp16
__device__ float  g_params[(size_t)MM * 96];    // [m][96]  (delta_in | b | c)
__device__ float  g_ppart[4][(size_t)MM * 96];  // split-K partials
__device__ __half g_dinh[(size_t)MM * RANK];    // fp16 delta_in for delta mma
__device__ float  g_delta[(size_t)MM * DI];     // softplus delta, [m][d]
__device__ __half g_yh[(size_t)MM * DI];        // scan output, [m][d] fp16

// fp16 operands for tensor-core GEMMs
__device__ __half g_A1h[(size_t)MM * DM];
__device__ __half g_B1h[(size_t)(2*DI) * DM];   // Win^T [N=4096][K=1024]
__device__ __half g_A3h[(size_t)MM * DI];       // gated y [4096][2048]
__device__ __half g_B3h[(size_t)DM * DI];       // Wout^T [N=1024][K=2048]
__device__ __half g_Wxh[(size_t)96 * DI];       // Wx^T  [96][2048]
__device__ __half g_Wdth[(size_t)DI * RANK];    // Wdt^T [2048][64]

// prep_kernel block budget (MUST sum to PREP_BLOCKS)
static constexpr int PB_CONV  = 4096;                       // convert_x
static constexpr int PB_WIN   = (2*DI/32) * (DM/32);        // 4096
static constexpr int PB_WOUT  = (DM/32) * (DI/32);          // 2048
static constexpr int PB_WX    = (96/32) * (DI/32);          // 192
static constexpr int PB_WDT   = (DI/32) * (RANK/32);        // 128
static constexpr int PREP_BLOCKS = PB_CONV + PB_WIN + PB_WOUT + PB_WX + PB_WDT;  // 10560

// ================= low-level helpers =================
__device__ __forceinline__ uint32_t smem_to_u32(const void* smem_ptr) {
    uint32_t addr;
    asm("{ .reg .u64 tmp; cvta.to.shared.u64 tmp, %1; cvt.u32.u64 %0, tmp; }"
        : "=r"(addr) : "l"(smem_ptr));
    return addr;
}
#define CP_ASYNC16(saddr, gaddr) \
    asm volatile("cp.async.cg.shared.global [%0], [%1], 16;" :: "r"(saddr), "l"(gaddr))
#define CP_COMMIT() asm volatile("cp.async.commit_group;" ::: "memory")
#define CP_WAIT(n)  asm volatile("cp.async.wait_group %0;" :: "n"(n) : "memory")

#define MBARRIER_INIT(mbar, count) \
    asm volatile("mbarrier.init.shared.b64 [%0], %1;" \
        :: "r"((uint32_t)(mbar)), "r"((uint32_t)(count)) : "memory")
#define MBARRIER_EXPECT_TX(mbar, tx) \
    asm volatile("mbarrier.arrive.expect_tx.shared.b64 _, [%0], %1;" \
        :: "r"((uint32_t)(mbar)), "r"((uint32_t)(tx)) : "memory")
#define TMA_LOAD_2D(dst, tmap, x, y, mbar) \
    asm volatile("cp.async.bulk.tensor.2d.shared::cta.global.tile.mbarrier::complete_tx::bytes " \
        "[%0], [%1, {%2, %3}], [%4];" \
        :: "r"((uint32_t)(dst)), "l"(tmap), "r"((int)(x)), "r"((int)(y)), "r"((uint32_t)(mbar)) : "memory")

#define MBARRIER_WAIT_PARITY(mbar_smem_addr, phase_parity) do { \
    uint32_t _mbar = (uint32_t)(mbar_smem_addr); \
    uint32_t _parity = (uint32_t)(phase_parity); \
    uint32_t _done; \
    asm volatile( \
        "{\n\t.reg .pred p;\n\t" \
        "mbarrier.try_wait.parity.acquire.cta.shared::cta.b64 p, [%1], %2;\n\t" \
        "selp.b32 %0, 1, 0, p;\n\t}" \
        : "=r"(_done) : "r"(_mbar), "r"(_parity) : "memory"); \
    if (!_done) { \
        asm volatile( \
            "{\n\t.reg .pred P1;\n\t" \
            "WAIT_LOOP_%=:\n\t" \
            "mbarrier.try_wait.parity.acquire.cta.shared::cta.b64 P1, [%0], %1, 0x989680;\n\t" \
            "@P1 bra.uni WAIT_DONE_%=;\n\t" \
            "bra.uni WAIT_LOOP_%=;\n\t" \
            "WAIT_DONE_%=:\n\t}" \
            :: "r"(_mbar), "r"(_parity) : "memory"); \
    } \
} while(0)

__device__ __forceinline__ void ldsm4(uint32_t* r, uint32_t addr) {
    asm volatile("ldmatrix.sync.aligned.m8n8.x4.shared.b16 {%0,%1,%2,%3}, [%4];"
        : "=r"(r[0]), "=r"(r[1]), "=r"(r[2]), "=r"(r[3]) : "r"(addr));
}
__device__ __forceinline__ void mma16816(float* d, const uint32_t* a, const uint32_t* b) {
    asm volatile(
        "mma.sync.aligned.m16n8k16.row.col.f32.f16.f16.f32 "
        "{%0,%1,%2,%3}, {%4,%5,%6,%7}, {%8,%9}, {%0,%1,%2,%3};"
        : "+f"(d[0]), "+f"(d[1]), "+f"(d[2]), "+f"(d[3])
        : "r"(a[0]), "r"(a[1]), "r"(a[2]), "r"(a[3]), "r"(b[0]), "r"(b[1]));
}
__device__ __forceinline__ uint32_t swz128(uint32_t o) {
    return o ^ ((o >> 3) & 0x70);
}

// ================= fused prep: convert_x + 4 weight transposes, one launch =================
__device__ __forceinline__ void tile_transpose(const float* __restrict__ src,
                                               __half* __restrict__ dst,
                                               int ND, int KD, int n0, int k0,
                                               float (*t)[33], int tx, int ty)
{
#pragma unroll
    for (int i = 0; i < 4; i++)
        t[ty + i*8][tx] = src[(size_t)(k0 + ty + i*8) * ND + n0 + tx];
    __syncthreads();
#pragma unroll
    for (int i = 0; i < 4; i++) {
        int n = n0 + ty + i*8, k = k0 + tx;
        dst[(size_t)n * KD + k] = __float2half_rn(t[tx][ty + i*8]);
    }
}

__global__ void prep_kernel(const float* __restrict__ x,   const float* __restrict__ Win,
                            const float* __restrict__ Wx,  const float* __restrict__ Wdt,
                            const float* __restrict__ Wout)
{
    __shared__ float t[32][33];
    int tid = threadIdx.x;
    int tx = tid & 31, ty = tid >> 5;
    int bid = blockIdx.x;

    if (bid < PB_CONV) {
        int i = bid * 256 + tid;
        float4 v = ((const float4*)x)[i];
        __half2 p0 = __floats2half2_rn(v.x, v.y);
        __half2 p1 = __floats2half2_rn(v.z, v.w);
        uint2 ph = make_uint2(*(uint32_t*)&p0, *(uint32_t*)&p1);
        *(uint2*)&g_A1h[(size_t)i*4] = ph;
        return;
    }
    bid -= PB_CONV;
    if (bid < PB_WIN) {
        int bx = bid & 127, by = bid >> 7;
        tile_transpose(Win, g_B1h, 2*DI, DM, bx*32, by*32, t, tx, ty);
        return;
    }
    bid -= PB_WIN;
    if (bid < PB_WOUT) {
        int bx = bid & 31, by = bid >> 5;
        tile_transpose(Wout, g_B3h, DM, DI, bx*32, by*32, t, tx, ty);
        return;
    }
    bid -= PB_WOUT;
    if (bid < PB_WX) {
        int bx = bid % 3, by = bid / 3;
        tile_transpose(Wx, g_Wxh, 96, DI, bx*32, by*32, t, tx, ty);
        return;
    }
    bid -= PB_WX;
    {
        int bx = bid & 63, by = bid >> 6;
        tile_transpose(Wdt, g_Wdth, DI, RANK, bx*32, by*32, t, tx, ty);
    }
}

__global__ void gate_convert_kernel()   // A3 = y * silu(z), fp16 in/out
{
    int i = blockIdx.x * 256 + threadIdx.x;
    size_t e = (size_t)i * 4;
    uint2 yp = *(const uint2*)&g_yh[e];
    uint2 zp = *(const uint2*)&g_zh[e];
    float2 y0 = __half22float2(*(__half2*)&yp.x);
    float2 y1 = __half22float2(*(__half2*)&yp.y);
    float2 z0 = __half22float2(*(__half2*)&zp.x);
    float2 z1 = __half22float2(*(__half2*)&zp.y);
    float a0 = y0.x * z0.x / (1.f + __expf(-z0.x));
    float a1 = y0.y * z0.y / (1.f + __expf(-z0.y));
    float a2 = y1.x * z1.x / (1.f + __expf(-z1.x));
    float a3 = y1.y * z1.y / (1.f + __expf(-z1.y));
    __half2 p0 = __floats2half2_rn(a0, a1);
    __half2 p1 = __floats2half2_rn(a2, a3);
    uint2 ph = make_uint2(*(uint32_t*)&p0, *(uint32_t*)&p1);
    *(uint2*)&g_A3h[e] = ph;
}

// ================= main GEMM: TMA tensor loads (SW128), k-chunk 64, 3-stage ring =================
static constexpr uint32_t TILE16K = 128u * 128u;
static constexpr uint32_t STG = 2u * TILE16K;
static constexpr uint32_t GSMEM_B = 2048u + 3u * STG;
static constexpr uint32_t TXB = 2u * TILE16K;

template<int WHICH>
__global__ __launch_bounds__(256, 2)
void mma_gemm_kernel(const __grid_constant__ CUtensorMap tmA,
                     const __grid_constant__ CUtensorMap tmB,
                     float* __restrict__ Cout)
{
    constexpr int KTOT = (WHICH == 1) ? DM : DI;
    constexpr int NC = KTOT / 64;

    extern __shared__ __align__(16) char smem[];
    uint32_t sb = smem_to_u32(smem);
    uint32_t tiles = (sb + 1024u + 1023u) & ~1023u;

    int tid = threadIdx.x;
    int lane = tid & 31, wid = tid >> 5;
    int wm = wid & 3, wn = wid >> 2;
    int m0 = blockIdx.y * 128;
    int n0 = blockIdx.x * 128;

    if (tid == 0) {
        MBARRIER_INIT(sb + 0, 1);
        MBARRIER_INIT(sb + 8, 1);
        MBARRIER_INIT(sb + 16, 1);
    }
    __syncthreads();

    auto issue = [&](int kc) {
        int st = kc % 3;
        uint32_t mb = sb + 8u * st;
        uint32_t base = tiles + st * STG;
        if (tid == 0) {
            MBARRIER_EXPECT_TX(mb, TXB);
            TMA_LOAD_2D(base,           &tmA, kc * 64, m0, mb);
            TMA_LOAD_2D(base + TILE16K, &tmB, kc * 64, n0, mb);
        }
    };

    issue(0); issue(1); issue(2);

    float d[2][8][4];
#pragma unroll
    for (int mt = 0; mt < 2; mt++)
#pragma unroll
        for (int nt = 0; nt < 8; nt++)
#pragma unroll
            for (int i = 0; i < 4; i++) d[mt][nt][i] = 0.f;

    int quad = lane >> 3, lrow = lane & 7;

    for (int kc = 0; kc < NC; kc++) {
        int st = kc % 3;
        MBARRIER_WAIT_PARITY(sb + 8u * st, (kc / 3) & 1);
        uint32_t bA = tiles + st * STG;
        uint32_t bB = bA + TILE16K;
#pragma unroll
        for (int ks = 0; ks < 4; ks++) {
            uint32_t aH[2][4];
#pragma unroll
            for (int mt = 0; mt < 2; mt++) {
                int row = wm * 32 + mt * 16 + (quad & 1) * 8 + lrow;
                uint32_t lin = (uint32_t)(row * 128) + (uint32_t)(ks * 32 + (quad >> 1) * 16);
                ldsm4(aH[mt], bA + swz128(lin));
            }
            uint32_t bH[8][2];
#pragma unroll
            for (int np = 0; np < 4; np++) {
                int nrow = wn * 64 + np * 16 + (quad >> 1) * 8 + lrow;
                uint32_t lin = (uint32_t)(nrow * 128) + (uint32_t)(ks * 32 + (quad & 1) * 16);
                uint32_t t[4];
                ldsm4(t, bB + swz128(lin));
                bH[np*2][0] = t[0]; bH[np*2][1] = t[1];
                bH[np*2+1][0] = t[2]; bH[np*2+1][1] = t[3];
            }
#pragma unroll
            for (int mt = 0; mt < 2; mt++)
#pragma unroll
                for (int nt = 0; nt < 8; nt++)
                    mma16816(d[mt][nt], aH[mt], bH[nt]);
        }
        __syncthreads();
        if (kc + 3 < NC) issue(kc + 3);
    }

    if (WHICH == 1) {
        bool isx = (n0 < DI);
#pragma unroll
        for (int mt = 0; mt < 2; mt++)
#pragma unroll
            for (int nt = 0; nt < 8; nt++) {
                int row = m0 + wm * 32 + mt * 16 + (lane >> 2);
                int col = n0 + wn * 64 + nt * 8 + (lane & 3) * 2;
                if (isx) {
                    float2 v0 = {d[mt][nt][0], d[mt][nt][1]};
                    float2 v1 = {d[mt][nt][2], d[mt][nt][3]};
                    *(float2*)&g_xf32[(size_t)row * DI + col] = v0;
                    *(float2*)&g_xf32[(size_t)(row + 8) * DI + col] = v1;
                } else {
                    int zc = col - DI;
                    __half2 h0 = __floats2half2_rn(d[mt][nt][0], d[mt][nt][1]);
                    __half2 h1 = __floats2half2_rn(d[mt][nt][2], d[mt][nt][3]);
                    *(__half2*)&g_zh[(size_t)row * DI + zc] = h0;
                    *(__half2*)&g_zh[(size_t)(row + 8) * DI + zc] = h1;
                }
            }
    } else {
#pragma unroll
        for (int mt = 0; mt < 2; mt++)
#pragma unroll
            for (int nt = 0; nt < 8; nt++) {
                int row = m0 + wm * 32 + mt * 16 + (lane >> 2);
                int col = n0 + wn * 64 + nt * 8 + (lane & 3) * 2;
                float2 v0 = {d[mt][nt][0], d[mt][nt][1]};
                float2 v1 = {d[mt][nt][2], d[mt][nt][3]};
                *(float2*)&Cout[(size_t)row * DM + col] = v0;
                *(float2*)&Cout[(size_t)(row + 8) * DM + col] = v1;
            }
    }
}

// ---------------- conv: float2 sliding window, 2 ch/thread, fp16 output only ----------------
__global__ __launch_bounds__(128)
void conv_kernel(const float* __restrict__ Wconv, const float* __restrict__ bconv)
{
    int tid = threadIdx.x;
    int b  = blockIdx.z;
    int c  = blockIdx.y * 256 + tid * 2;
    int s0 = blockIdx.x * 16;

    float4 w0 = ((const float4*)Wconv)[c + 0];
    float4 w1 = ((const float4*)Wconv)[c + 1];
    float2 bs = *(const float2*)&bconv[c];

    const float* xin = g_xf32 + (size_t)b * SS * DI + c;
    __half* hout = g_xbch + (size_t)b * SS * DI + c;

    float2 xm3, xm2, xm1;
    float2 z2 = {0.f, 0.f};
    xm3 = (s0 >= 3) ? *(const float2*)&xin[(size_t)(s0 - 3) * DI] : z2;
    xm2 = (s0 >= 2) ? *(const float2*)&xin[(size_t)(s0 - 2) * DI] : z2;
    xm1 = (s0 >= 1) ? *(const float2*)&xin[(size_t)(s0 - 1) * DI] : z2;

#pragma unroll 4
    for (int r = 0; r < 16; r++) {
        float2 x0 = *(const float2*)&xin[(size_t)(s0 + r) * DI];
        float2 o;
        o.x = bs.x + w0.x * xm3.x + w0.y * xm2.x + w0.z * xm1.x + w0.w * x0.x;
        o.y = bs.y + w1.x * xm3.y + w1.y * xm2.y + w1.z * xm1.y + w1.w * x0.y;
        o.x = o.x / (1.f + __expf(-o.x));
        o.y = o.y / (1.f + __expf(-o.y));
        __half2 h = __floats2half2_rn(o.x, o.y);
        *(__half2*)&hout[(size_t)(s0 + r) * DI] = h;
        xm3 = xm2; xm2 = xm1; xm1 = x0;
    }
}

// ---------------- params mma: split-K=4 -> g_ppart, then fixup ----------------
static constexpr int PTS = 72;
static constexpr int PKS = 4;                 // k-splits
static constexpr int PKC = DI / 64 / PKS;     // 8 chunks per split
__global__ __launch_bounds__(128)
void params_mma_kernel()
{
    __shared__ __align__(16) char ps[2 * (32 + 96) * PTS * 2];
    const uint32_t ST = (32 + 96) * PTS * 2;
    const uint32_t OB = 32 * PTS * 2;
    uint32_t sb = smem_to_u32(ps);

    int tid = threadIdx.x;
    int lane = tid & 31, wid = tid >> 5;
    int wm = wid & 1, wn = wid >> 1;
    int m0 = blockIdx.x * 32;
    int kspl = blockIdx.y;
    int kb0 = kspl * PKC * 64;

    float d[6][4];
#pragma unroll
    for (int nt = 0; nt < 6; nt++)
#pragma unroll
        for (int i = 0; i < 4; i++) d[nt][i] = 0.f;

    auto load_stage = [&](int stg, int kb) {
        uint32_t base = sb + stg * ST;
#pragma unroll
        for (int it = 0; it < 2; it++) {
            int u = tid + it * 128;
            int r = u >> 3, c8 = u & 7;
            CP_ASYNC16(base + (uint32_t)(r * PTS + c8 * 8) * 2,
                       g_xbch + (size_t)(m0 + r) * DI + kb + c8 * 8);
        }
#pragma unroll
        for (int it = 0; it < 6; it++) {
            int u = tid + it * 128;
            int r = u >> 3, c8 = u & 7;
            CP_ASYNC16(base + OB + (uint32_t)(r * PTS + c8 * 8) * 2,
                       g_Wxh + (size_t)r * DI + kb + c8 * 8);
        }
        CP_COMMIT();
    };

    load_stage(0, kb0);
    int quad = lane >> 3, lrow = lane & 7;

    for (int kc = 0; kc < PKC; kc++) {
        if (kc + 1 < PKC) { load_stage((kc + 1) & 1, kb0 + (kc + 1) * 64); CP_WAIT(1); }
        else CP_WAIT(0);
        __syncthreads();
        uint32_t base = sb + (kc & 1) * ST;
#pragma unroll
        for (int ks = 0; ks < 4; ks++) {
            int k16 = ks * 16;
            uint32_t aH[4];
            {
                int row = wm * 16 + (quad & 1) * 8 + lrow;
                ldsm4(aH, base + (uint32_t)(row * PTS + k16 + (quad >> 1) * 8) * 2);
            }
            uint32_t bH[6][2];
#pragma unroll
            for (int np = 0; np < 3; np++) {
                int nrow = wn * 48 + np * 16 + (quad >> 1) * 8 + lrow;
                uint32_t t[4];
                ldsm4(t, base + OB + (uint32_t)(nrow * PTS + k16 + (quad & 1) * 8) * 2);
                bH[np*2][0] = t[0]; bH[np*2][1] = t[1];
                bH[np*2+1][0] = t[2]; bH[np*2+1][1] = t[3];
            }
#pragma unroll
            for (int nt = 0; nt < 6; nt++)
                mma16816(d[nt], aH, bH[nt]);
        }
        __syncthreads();
    }

    float* pout = g_ppart[kspl];
#pragma unroll
    for (int nt = 0; nt < 6; nt++) {
        int row = m0 + wm * 16 + (lane >> 2);
        int col = wn * 48 + nt * 8 + (lane & 3) * 2;
        float2 v0 = {d[nt][0], d[nt][1]};
        float2 v1 = {d[nt][2], d[nt][3]};
        *(float2*)&pout[(size_t)row * 96 + col] = v0;
        *(float2*)&pout[(size_t)(row + 8) * 96 + col] = v1;
    }
}

// sums the 4 partials; writes g_params and g_dinh (fp16 for cols<64)
__global__ __launch_bounds__(256)
void params_fix_kernel()
{
    int idx = blockIdx.x * 256 + threadIdx.x;     // 0 .. MM*96-1
    int row = idx / 96, col = idx - row * 96;
    float s = g_ppart[0][idx] + g_ppart[1][idx] + g_ppart[2][idx] + g_ppart[3][idx];
    g_params[idx] = s;
    if (col < 64)
        g_dinh[(size_t)row * 64 + col] = __float2half_rn(s);
}

// ---------------- delta mma: g_delta[m][d] = softplus(delta_in @ Wdt + bdt) ----------------
__global__ __launch_bounds__(256)
void delta_mma_kernel(const float* __restrict__ bdt)
{
    __shared__ __align__(16) char ds[2 * 128 * PTS * 2];
    const uint32_t OB = 128 * PTS * 2;
    uint32_t sb = smem_to_u32(ds);

    int tid = threadIdx.x;
    int lane = tid & 31, wid = tid >> 5;
    int wm = wid & 3, wn = wid >> 2;
    int n0 = blockIdx.x * 128;
    int m0 = blockIdx.y * 128;

#pragma unroll
    for (int it = 0; it < 4; it++) {
        int u = tid + it * 256;
        int r = u >> 3, c8 = u & 7;
        CP_ASYNC16(sb + (uint32_t)(r * PTS + c8 * 8) * 2,
                   g_dinh + (size_t)(m0 + r) * 64 + c8 * 8);
    }
#pragma unroll
    for (int it = 0; it < 4; it++) {
        int u = tid + it * 256;
        int r = u >> 3, c8 = u & 7;
        CP_ASYNC16(sb + OB + (uint32_t)(r * PTS + c8 * 8) * 2,
                   g_Wdth + (size_t)(n0 + r) * 64 + c8 * 8);
    }
    CP_COMMIT();

    float d[2][8][4];
#pragma unroll
    for (int mt = 0; mt < 2; mt++)
#pragma unroll
        for (int nt = 0; nt < 8; nt++)
#pragma unroll
            for (int i = 0; i < 4; i++) d[mt][nt][i] = 0.f;

    CP_WAIT(0);
    __syncthreads();

    int quad = lane >> 3, lrow = lane & 7;
#pragma unroll
    for (int ks = 0; ks < 4; ks++) {
        int k16 = ks * 16;
        uint32_t aH[2][4];
#pragma unroll
        for (int mt = 0; mt < 2; mt++) {
            int row = wm * 32 + mt * 16 + (quad & 1) * 8 + lrow;
            ldsm4(aH[mt], sb + (uint32_t)(row * PTS + k16 + (quad >> 1) * 8) * 2);
        }
        uint32_t bH[8][2];
#pragma unroll
        for (int np = 0; np < 4; np++) {
            int nrow = wn * 64 + np * 16 + (quad >> 1) * 8 + lrow;
            uint32_t t[4];
            ldsm4(t, sb + OB + (uint32_t)(nrow * PTS + k16 + (quad & 1) * 8) * 2);
            bH[np*2][0] = t[0]; bH[np*2][1] = t[1];
            bH[np*2+1][0] = t[2]; bH[np*2+1][1] = t[3];
        }
#pragma unroll
        for (int mt = 0; mt < 2; mt++)
#pragma unroll
            for (int nt = 0; nt < 8; nt++)
                mma16816(d[mt][nt], aH[mt], bH[nt]);
    }

#pragma unroll
    for (int mt = 0; mt < 2; mt++)
#pragma unroll
        for (int nt = 0; nt < 8; nt++) {
            int row = m0 + wm * 32 + mt * 16 + (lane >> 2);
            int col = n0 + wn * 64 + nt * 8 + (lane & 3) * 2;
            float b0 = bdt[col], b1 = bdt[col + 1];
#pragma unroll
            for (int h = 0; h < 2; h++) {
                float t0 = d[mt][nt][h*2+0] + b0;
                float t1 = d[mt][nt][h*2+1] + b1;
                float2 v;
                v.x = fmaxf(t0, 0.f) + log1pf(__expf(-fabsf(t0)));
                v.y = fmaxf(t1, 0.f) + log1pf(__expf(-fabsf(t1)));
                *(float2*)&g_delta[(size_t)(row + h*8) * DI + col] = v;
            }
        }
}

// ---------------- selective scan: 8 lanes/channel, 2 states/lane; u fp16 in, y fp16 out ----------------
__global__ __launch_bounds__(128, 8)
void scan_kernel(const float* __restrict__ A_log, const float* __restrict__ Dp)
{
    __shared__ float2 sh_duu[32][16];
    __shared__ float  sh_bc[32][32];
    __shared__ float  sh_y[32][16];
    int tid = threadIdx.x;
    int lane = tid & 31, w = tid >> 5;
    int gch0 = blockIdx.x * 16;
    int b  = gch0 / DI;
    int d0 = gch0 % DI;
    int q  = lane & 7;
    int ch = w * 4 + (lane >> 3);
    int d  = d0 + ch;

    float an0, an1;
    {
        float2 al = *(const float2*)&A_log[(size_t)d * DSTATE + 2 * q];
        an0 = -__expf(al.x) * 1.44269504f;
        an1 = -__expf(al.y) * 1.44269504f;
    }
    float dpv = Dp[d];
    float s0 = 0.f, s1 = 0.f;

    const float*  dmb = g_delta + (size_t)b * SS * DI + d0;
    const __half* umb = g_xbch + (size_t)b * SS * DI + d0;
    const float*  pmb = g_params + (size_t)b * SS * 96 + 64;
    __half* ymb = g_yh + (size_t)b * SS * DI + d0;

    for (int t0 = 0; t0 < SS; t0 += 32) {
#pragma unroll
        for (int k = 0; k < 4; k++) {
            int idx = tid + k * 128;
            int i = idx >> 4, j = idx & 15;
            size_t off = (size_t)(t0 + i) * DI + j;
            sh_duu[i][j] = make_float2(dmb[off], __half2float(umb[off]));
        }
#pragma unroll
        for (int k = 0; k < 8; k++) {
            int idx = tid + k * 128;
            int i = idx >> 5, j = idx & 31;
            sh_bc[i][j] = pmb[(size_t)(t0 + i) * 96 + j];
        }
        __syncthreads();

#pragma unroll 4
        for (int i = 0; i < 32; i++) {
            float2 duu = sh_duu[i][ch];
            float2 bq = *(float2*)&sh_bc[i][2 * q];
            float2 cq = *(float2*)&sh_bc[i][16 + 2 * q];
            float du = duu.x * duu.y;
            float e0 = exp2f(duu.x * an0);
            float e1 = exp2f(duu.x * an1);
            s0 = fmaf(e0, s0, du * bq.x);
            s1 = fmaf(e1, s1, du * bq.y);
            float acc = fmaf(s1, cq.y, s0 * cq.x);
            acc += __shfl_xor_sync(0xffffffffu, acc, 1);
            acc += __shfl_xor_sync(0xffffffffu, acc, 2);
            acc += __shfl_xor_sync(0xffffffffu, acc, 4);
            if (q == 0) sh_y[i][ch] = fmaf(duu.y, dpv, acc);
        }
        __syncthreads();
#pragma unroll
        for (int k = 0; k < 2; k++) {
            int idx = tid + k * 128;
            int i = idx >> 3, j = idx & 7;
            __half2 hv = __floats2half2_rn(sh_y[i][2*j], sh_y[i][2*j + 1]);
            *(__half2*)&ymb[(size_t)(t0 + i) * DI + 2*j] = hv;
        }
    }
}

// ---------------- host: tensor-map plumbing ----------------
typedef CUresult (*EncodeFn)(CUtensorMap*, CUtensorMapDataType, cuuint32_t, void*,
                             const cuuint64_t*, const cuuint64_t*, const cuuint32_t*,
                             const cuuint32_t*, CUtensorMapInterleave, CUtensorMapSwizzle,
                             CUtensorMapL2promotion, CUtensorMapFloatOOBfill);

static EncodeFn get_encode_fn()
{
    static EncodeFn fn = nullptr;
    if (!fn) {
        void* p = nullptr;
        cudaDriverEntryPointQueryResult qr;
        cudaGetDriverEntryPointByVersion("cuTensorMapEncodeTiled", &p, 12000,
                                         cudaEnableDefault, &qr);
        fn = (EncodeFn)p;
    }
    return fn;
}

static void make_tm(CUtensorMap* tm, void* gaddr, uint64_t kdim, uint64_t rows)
{
    cuuint64_t dims[2]    = {kdim, rows};
    cuuint64_t strides[1] = {kdim * 2};
    cuuint32_t box[2]     = {64, 128};
    cuuint32_t es[2]      = {1, 1};
    get_encode_fn()(tm, CU_TENSOR_MAP_DATA_TYPE_FLOAT16, 2, gaddr,
                    dims, strides, box, es,
                    CU_TENSOR_MAP_INTERLEAVE_NONE, CU_TENSOR_MAP_SWIZZLE_128B,
                    CU_TENSOR_MAP_L2_PROMOTION_L2_128B,
                    CU_TENSOR_MAP_FLOAT_OOB_FILL_NONE);
}

// ---------------- launch ----------------
extern "C" void kernel_launch(void* const* d_in, const int* in_sizes, int n_in,
                              void* d_out, int out_size)
{
    (void)in_sizes; (void)n_in; (void)out_size;
    const float* x     = (const float*)d_in[0];
    const float* Win   = (const float*)d_in[1];
    const float* Wconv = (const float*)d_in[2];
    const float* bconv = (const float*)d_in[3];
    const float* Wx    = (const float*)d_in[4];
    const float* Wdt   = (const float*)d_in[5];
    const float* bdt   = (const float*)d_in[6];
    const float* A_log = (const float*)d_in[7];
    const float* Dp    = (const float*)d_in[8];
    const float* Wout  = (const float*)d_in[9];
    float* out = (float*)d_out;

    void *pA1h, *pB1h, *pA3h, *pB3h;
    cudaGetSymbolAddress(&pA1h, g_A1h);
    cudaGetSymbolAddress(&pB1h, g_B1h);
    cudaGetSymbolAddress(&pA3h, g_A3h);
    cudaGetSymbolAddress(&pB3h, g_B3h);

    CUtensorMap tmA1, tmB1, tmA3, tmB3;
    make_tm(&tmA1, pA1h, DM, MM);
    make_tm(&tmB1, pB1h, DM, 2*DI);
    make_tm(&tmA3, pA3h, DI, MM);
    make_tm(&tmB3, pB3h, DI, DM);

    cudaFuncSetAttribute(mma_gemm_kernel<1>, cudaFuncAttributeMaxDynamicSharedMemorySize, GSMEM_B);
    cudaFuncSetAttribute(mma_gemm_kernel<3>, cudaFuncAttributeMaxDynamicSharedMemorySize, GSMEM_B);

    prep_kernel<<<PREP_BLOCKS, 256>>>(x, Win, Wx, Wdt, Wout);
    mma_gemm_kernel<1><<<dim3(32, 32), 256, GSMEM_B>>>(tmA1, tmB1, nullptr);
    conv_kernel<<<dim3(SS / 16, DI / 256, BB), 128>>>(Wconv, bconv);
    params_mma_kernel<<<dim3(128, PKS), 128>>>();
    params_fix_kernel<<<MM * 96 / 256, 256>>>();
    delta_mma_kernel<<<dim3(16, 32), 256>>>(bdt);
    scan_kernel<<<256, 128>>>(A_log, Dp);
    gate_convert_kernel<<<8192, 256>>>();
    mma_gemm_kernel<3><<<dim3(8, 32), 256, GSMEM_B>>>(tmA3, tmB3, out);
}

// round 15
// speedup vs baseline: 1.2186x; 1.0158x over previous
#include <cuda_runtime.h>
#include <cuda.h>
#include <cuda_fp16.h>
#include <math.h>
#include <stdint.h>

#define BB 2
#define SS 2048
#define DM 1024
#define DI 2048
#define DSTATE 16
#define RANK 64
#define MM (BB*SS)   /* 4096 rows (b,s) */

// ---------------- scratch (static device globals; no runtime allocation) ----------------
__device__ float  g_xf32[(size_t)MM * DI];      // GEMM1 x-branch, [m][d] fp32
__device__ __half g_zh[(size_t)MM * DI];        // GEMM1 z-branch, [m][d] fp16
__device__ __half g_xbch[(size_t)MM * DI];      // conv+silu (u), [m][d] fp16
__device__ float  g_params[(size_t)MM * 96];    // [m][96]  (delta_in | b | c)
__device__ float  g_ppart[4][(size_t)MM * 96];  // split-K partials
__device__ __half g_dinh[(size_t)MM * RANK];    // fp16 delta_in for delta mma
__device__ float  g_delta[(size_t)MM * DI];     // softplus delta, [m][d]
__device__ __half g_yh[(size_t)MM * DI];        // scan output, [m][d] fp16

// fp16 operands for tensor-core GEMMs
__device__ __half g_A1h[(size_t)MM * DM];
__device__ __half g_B1h[(size_t)(2*DI) * DM];   // Win^T [N=4096][K=1024]
__device__ __half g_A3h[(size_t)MM * DI];       // gated y [4096][2048]
__device__ __half g_B3h[(size_t)DM * DI];       // Wout^T [N=1024][K=2048]
__device__ __half g_Wxh[(size_t)96 * DI];       // Wx^T  [96][2048]
__device__ __half g_Wdth[(size_t)DI * RANK];    // Wdt^T [2048][64]

// prep_kernel block budget (MUST sum to PREP_BLOCKS)
static constexpr int PB_CONV  = 4096;
static constexpr int PB_WIN   = (2*DI/32) * (DM/32);        // 4096
static constexpr int PB_WOUT  = (DM/32) * (DI/32);          // 2048
static constexpr int PB_WX    = (96/32) * (DI/32);          // 192
static constexpr int PB_WDT   = (DI/32) * (RANK/32);        // 128
static constexpr int PREP_BLOCKS = PB_CONV + PB_WIN + PB_WOUT + PB_WX + PB_WDT;  // 10560

// ================= low-level helpers =================
__device__ __forceinline__ uint32_t smem_to_u32(const void* smem_ptr) {
    uint32_t addr;
    asm("{ .reg .u64 tmp; cvta.to.shared.u64 tmp, %1; cvt.u32.u64 %0, tmp; }"
        : "=r"(addr) : "l"(smem_ptr));
    return addr;
}
#define CP_ASYNC16(saddr, gaddr) \
    asm volatile("cp.async.cg.shared.global [%0], [%1], 16;" :: "r"(saddr), "l"(gaddr))
#define CP_COMMIT() asm volatile("cp.async.commit_group;" ::: "memory")
#define CP_WAIT(n)  asm volatile("cp.async.wait_group %0;" :: "n"(n) : "memory")

#define MBARRIER_INIT(mbar, count) \
    asm volatile("mbarrier.init.shared.b64 [%0], %1;" \
        :: "r"((uint32_t)(mbar)), "r"((uint32_t)(count)) : "memory")
#define MBARRIER_EXPECT_TX(mbar, tx) \
    asm volatile("mbarrier.arrive.expect_tx.shared.b64 _, [%0], %1;" \
        :: "r"((uint32_t)(mbar)), "r"((uint32_t)(tx)) : "memory")
#define TMA_LOAD_2D(dst, tmap, x, y, mbar) \
    asm volatile("cp.async.bulk.tensor.2d.shared::cta.global.tile.mbarrier::complete_tx::bytes " \
        "[%0], [%1, {%2, %3}], [%4];" \
        :: "r"((uint32_t)(dst)), "l"(tmap), "r"((int)(x)), "r"((int)(y)), "r"((uint32_t)(mbar)) : "memory")

#define MBARRIER_WAIT_PARITY(mbar_smem_addr, phase_parity) do { \
    uint32_t _mbar = (uint32_t)(mbar_smem_addr); \
    uint32_t _parity = (uint32_t)(phase_parity); \
    uint32_t _done; \
    asm volatile( \
        "{\n\t.reg .pred p;\n\t" \
        "mbarrier.try_wait.parity.acquire.cta.shared::cta.b64 p, [%1], %2;\n\t" \
        "selp.b32 %0, 1, 0, p;\n\t}" \
        : "=r"(_done) : "r"(_mbar), "r"(_parity) : "memory"); \
    if (!_done) { \
        asm volatile( \
            "{\n\t.reg .pred P1;\n\t" \
            "WAIT_LOOP_%=:\n\t" \
            "mbarrier.try_wait.parity.acquire.cta.shared::cta.b64 P1, [%0], %1, 0x989680;\n\t" \
            "@P1 bra.uni WAIT_DONE_%=;\n\t" \
            "bra.uni WAIT_LOOP_%=;\n\t" \
            "WAIT_DONE_%=:\n\t}" \
            :: "r"(_mbar), "r"(_parity) : "memory"); \
    } \
} while(0)

__device__ __forceinline__ void ldsm4(uint32_t* r, uint32_t addr) {
    asm volatile("ldmatrix.sync.aligned.m8n8.x4.shared.b16 {%0,%1,%2,%3}, [%4];"
        : "=r"(r[0]), "=r"(r[1]), "=r"(r[2]), "=r"(r[3]) : "r"(addr));
}
__device__ __forceinline__ void mma16816(float* d, const uint32_t* a, const uint32_t* b) {
    asm volatile(
        "mma.sync.aligned.m16n8k16.row.col.f32.f16.f16.f32 "
        "{%0,%1,%2,%3}, {%4,%5,%6,%7}, {%8,%9}, {%0,%1,%2,%3};"
        : "+f"(d[0]), "+f"(d[1]), "+f"(d[2]), "+f"(d[3])
        : "r"(a[0]), "r"(a[1]), "r"(a[2]), "r"(a[3]), "r"(b[0]), "r"(b[1]));
}
__device__ __forceinline__ uint32_t swz128(uint32_t o) {
    return o ^ ((o >> 3) & 0x70);
}

// ================= fused prep: convert_x + 4 weight transposes, one launch =================
__device__ __forceinline__ void tile_transpose(const float* __restrict__ src,
                                               __half* __restrict__ dst,
                                               int ND, int KD, int n0, int k0,
                                               float (*t)[33], int tx, int ty)
{
#pragma unroll
    for (int i = 0; i < 4; i++)
        t[ty + i*8][tx] = src[(size_t)(k0 + ty + i*8) * ND + n0 + tx];
    __syncthreads();
#pragma unroll
    for (int i = 0; i < 4; i++) {
        int n = n0 + ty + i*8, k = k0 + tx;
        dst[(size_t)n * KD + k] = __float2half_rn(t[tx][ty + i*8]);
    }
}

__global__ void prep_kernel(const float* __restrict__ x,   const float* __restrict__ Win,
                            const float* __restrict__ Wx,  const float* __restrict__ Wdt,
                            const float* __restrict__ Wout)
{
    __shared__ float t[32][33];
    int tid = threadIdx.x;
    int tx = tid & 31, ty = tid >> 5;
    int bid = blockIdx.x;

    if (bid < PB_CONV) {
        int i = bid * 256 + tid;
        float4 v = ((const float4*)x)[i];
        __half2 p0 = __floats2half2_rn(v.x, v.y);
        __half2 p1 = __floats2half2_rn(v.z, v.w);
        uint2 ph = make_uint2(*(uint32_t*)&p0, *(uint32_t*)&p1);
        *(uint2*)&g_A1h[(size_t)i*4] = ph;
        return;
    }
    bid -= PB_CONV;
    if (bid < PB_WIN) {
        int bx = bid & 127, by = bid >> 7;
        tile_transpose(Win, g_B1h, 2*DI, DM, bx*32, by*32, t, tx, ty);
        return;
    }
    bid -= PB_WIN;
    if (bid < PB_WOUT) {
        int bx = bid & 31, by = bid >> 5;
        tile_transpose(Wout, g_B3h, DM, DI, bx*32, by*32, t, tx, ty);
        return;
    }
    bid -= PB_WOUT;
    if (bid < PB_WX) {
        int bx = bid % 3, by = bid / 3;
        tile_transpose(Wx, g_Wxh, 96, DI, bx*32, by*32, t, tx, ty);
        return;
    }
    bid -= PB_WX;
    {
        int bx = bid & 63, by = bid >> 6;
        tile_transpose(Wdt, g_Wdth, DI, RANK, bx*32, by*32, t, tx, ty);
    }
}

__global__ void gate_convert_kernel()   // A3 = y * silu(z), fp16 in/out
{
    int i = blockIdx.x * 256 + threadIdx.x;
    size_t e = (size_t)i * 4;
    uint2 yp = *(const uint2*)&g_yh[e];
    uint2 zp = *(const uint2*)&g_zh[e];
    float2 y0 = __half22float2(*(__half2*)&yp.x);
    float2 y1 = __half22float2(*(__half2*)&yp.y);
    float2 z0 = __half22float2(*(__half2*)&zp.x);
    float2 z1 = __half22float2(*(__half2*)&zp.y);
    float a0 = y0.x * z0.x / (1.f + __expf(-z0.x));
    float a1 = y0.y * z0.y / (1.f + __expf(-z0.y));
    float a2 = y1.x * z1.x / (1.f + __expf(-z1.x));
    float a3 = y1.y * z1.y / (1.f + __expf(-z1.y));
    __half2 p0 = __floats2half2_rn(a0, a1);
    __half2 p1 = __floats2half2_rn(a2, a3);
    uint2 ph = make_uint2(*(uint32_t*)&p0, *(uint32_t*)&p1);
    *(uint2*)&g_A3h[e] = ph;
}

// ================= main GEMM: TMA tensor loads (SW128), k-chunk 64, 3-stage ring =================
static constexpr uint32_t TILE16K = 128u * 128u;
static constexpr uint32_t STG = 2u * TILE16K;
static constexpr uint32_t GSMEM_B = 2048u + 3u * STG;
static constexpr uint32_t TXB = 2u * TILE16K;

template<int WHICH>
__global__ __launch_bounds__(256, 2)
void mma_gemm_kernel(const __grid_constant__ CUtensorMap tmA,
                     const __grid_constant__ CUtensorMap tmB,
                     float* __restrict__ Cout, int n_base)
{
    constexpr int KTOT = (WHICH == 1) ? DM : DI;
    constexpr int NC = KTOT / 64;

    extern __shared__ __align__(16) char smem[];
    uint32_t sb = smem_to_u32(smem);
    uint32_t tiles = (sb + 1024u + 1023u) & ~1023u;

    int tid = threadIdx.x;
    int lane = tid & 31, wid = tid >> 5;
    int wm = wid & 3, wn = wid >> 2;
    int m0 = blockIdx.y * 128;
    int n0 = n_base + blockIdx.x * 128;

    if (tid == 0) {
        MBARRIER_INIT(sb + 0, 1);
        MBARRIER_INIT(sb + 8, 1);
        MBARRIER_INIT(sb + 16, 1);
    }
    __syncthreads();

    auto issue = [&](int kc) {
        int st = kc % 3;
        uint32_t mb = sb + 8u * st;
        uint32_t base = tiles + st * STG;
        if (tid == 0) {
            MBARRIER_EXPECT_TX(mb, TXB);
            TMA_LOAD_2D(base,           &tmA, kc * 64, m0, mb);
            TMA_LOAD_2D(base + TILE16K, &tmB, kc * 64, n0, mb);
        }
    };

    issue(0); issue(1); issue(2);

    float d[2][8][4];
#pragma unroll
    for (int mt = 0; mt < 2; mt++)
#pragma unroll
        for (int nt = 0; nt < 8; nt++)
#pragma unroll
            for (int i = 0; i < 4; i++) d[mt][nt][i] = 0.f;

    int quad = lane >> 3, lrow = lane & 7;

    for (int kc = 0; kc < NC; kc++) {
        int st = kc % 3;
        MBARRIER_WAIT_PARITY(sb + 8u * st, (kc / 3) & 1);
        uint32_t bA = tiles + st * STG;
        uint32_t bB = bA + TILE16K;
#pragma unroll
        for (int ks = 0; ks < 4; ks++) {
            uint32_t aH[2][4];
#pragma unroll
            for (int mt = 0; mt < 2; mt++) {
                int row = wm * 32 + mt * 16 + (quad & 1) * 8 + lrow;
                uint32_t lin = (uint32_t)(row * 128) + (uint32_t)(ks * 32 + (quad >> 1) * 16);
                ldsm4(aH[mt], bA + swz128(lin));
            }
            uint32_t bH[8][2];
#pragma unroll
            for (int np = 0; np < 4; np++) {
                int nrow = wn * 64 + np * 16 + (quad >> 1) * 8 + lrow;
                uint32_t lin = (uint32_t)(nrow * 128) + (uint32_t)(ks * 32 + (quad & 1) * 16);
                uint32_t t[4];
                ldsm4(t, bB + swz128(lin));
                bH[np*2][0] = t[0]; bH[np*2][1] = t[1];
                bH[np*2+1][0] = t[2]; bH[np*2+1][1] = t[3];
            }
#pragma unroll
            for (int mt = 0; mt < 2; mt++)
#pragma unroll
                for (int nt = 0; nt < 8; nt++)
                    mma16816(d[mt][nt], aH[mt], bH[nt]);
        }
        __syncthreads();
        if (kc + 3 < NC) issue(kc + 3);
    }

    if (WHICH == 1) {
        bool isx = (n0 < DI);
#pragma unroll
        for (int mt = 0; mt < 2; mt++)
#pragma unroll
            for (int nt = 0; nt < 8; nt++) {
                int row = m0 + wm * 32 + mt * 16 + (lane >> 2);
                int col = n0 + wn * 64 + nt * 8 + (lane & 3) * 2;
                if (isx) {
                    float2 v0 = {d[mt][nt][0], d[mt][nt][1]};
                    float2 v1 = {d[mt][nt][2], d[mt][nt][3]};
                    *(float2*)&g_xf32[(size_t)row * DI + col] = v0;
                    *(float2*)&g_xf32[(size_t)(row + 8) * DI + col] = v1;
                } else {
                    int zc = col - DI;
                    __half2 h0 = __floats2half2_rn(d[mt][nt][0], d[mt][nt][1]);
                    __half2 h1 = __floats2half2_rn(d[mt][nt][2], d[mt][nt][3]);
                    *(__half2*)&g_zh[(size_t)row * DI + zc] = h0;
                    *(__half2*)&g_zh[(size_t)(row + 8) * DI + zc] = h1;
                }
            }
    } else {
#pragma unroll
        for (int mt = 0; mt < 2; mt++)
#pragma unroll
            for (int nt = 0; nt < 8; nt++) {
                int row = m0 + wm * 32 + mt * 16 + (lane >> 2);
                int col = n0 + wn * 64 + nt * 8 + (lane & 3) * 2;
                float2 v0 = {d[mt][nt][0], d[mt][nt][1]};
                float2 v1 = {d[mt][nt][2], d[mt][nt][3]};
                *(float2*)&Cout[(size_t)row * DM + col] = v0;
                *(float2*)&Cout[(size_t)(row + 8) * DM + col] = v1;
            }
    }
}

// ---------------- conv: float2 sliding window, 2 ch/thread, fp16 output only ----------------
__global__ __launch_bounds__(128)
void conv_kernel(const float* __restrict__ Wconv, const float* __restrict__ bconv)
{
    int tid = threadIdx.x;
    int b  = blockIdx.z;
    int c  = blockIdx.y * 256 + tid * 2;
    int s0 = blockIdx.x * 16;

    float4 w0 = ((const float4*)Wconv)[c + 0];
    float4 w1 = ((const float4*)Wconv)[c + 1];
    float2 bs = *(const float2*)&bconv[c];

    const float* xin = g_xf32 + (size_t)b * SS * DI + c;
    __half* hout = g_xbch + (size_t)b * SS * DI + c;

    float2 xm3, xm2, xm1;
    float2 z2 = {0.f, 0.f};
    xm3 = (s0 >= 3) ? *(const float2*)&xin[(size_t)(s0 - 3) * DI] : z2;
    xm2 = (s0 >= 2) ? *(const float2*)&xin[(size_t)(s0 - 2) * DI] : z2;
    xm1 = (s0 >= 1) ? *(const float2*)&xin[(size_t)(s0 - 1) * DI] : z2;

#pragma unroll 4
    for (int r = 0; r < 16; r++) {
        float2 x0 = *(const float2*)&xin[(size_t)(s0 + r) * DI];
        float2 o;
        o.x = bs.x + w0.x * xm3.x + w0.y * xm2.x + w0.z * xm1.x + w0.w * x0.x;
        o.y = bs.y + w1.x * xm3.y + w1.y * xm2.y + w1.z * xm1.y + w1.w * x0.y;
        o.x = o.x / (1.f + __expf(-o.x));
        o.y = o.y / (1.f + __expf(-o.y));
        __half2 h = __floats2half2_rn(o.x, o.y);
        *(__half2*)&hout[(size_t)(s0 + r) * DI] = h;
        xm3 = xm2; xm2 = xm1; xm1 = x0;
    }
}

// ---------------- params mma: split-K=4 -> g_ppart, then fixup ----------------
static constexpr int PTS = 72;
static constexpr int PKS = 4;
static constexpr int PKC = DI / 64 / PKS;
__global__ __launch_bounds__(128)
void params_mma_kernel()
{
    __shared__ __align__(16) char ps[2 * (32 + 96) * PTS * 2];
    const uint32_t ST = (32 + 96) * PTS * 2;
    const uint32_t OB = 32 * PTS * 2;
    uint32_t sb = smem_to_u32(ps);

    int tid = threadIdx.x;
    int lane = tid & 31, wid = tid >> 5;
    int wm = wid & 1, wn = wid >> 1;
    int m0 = blockIdx.x * 32;
    int kspl = blockIdx.y;
    int kb0 = kspl * PKC * 64;

    float d[6][4];
#pragma unroll
    for (int nt = 0; nt < 6; nt++)
#pragma unroll
        for (int i = 0; i < 4; i++) d[nt][i] = 0.f;

    auto load_stage = [&](int stg, int kb) {
        uint32_t base = sb + stg * ST;
#pragma unroll
        for (int it = 0; it < 2; it++) {
            int u = tid + it * 128;
            int r = u >> 3, c8 = u & 7;
            CP_ASYNC16(base + (uint32_t)(r * PTS + c8 * 8) * 2,
                       g_xbch + (size_t)(m0 + r) * DI + kb + c8 * 8);
        }
#pragma unroll
        for (int it = 0; it < 6; it++) {
            int u = tid + it * 128;
            int r = u >> 3, c8 = u & 7;
            CP_ASYNC16(base + OB + (uint32_t)(r * PTS + c8 * 8) * 2,
                       g_Wxh + (size_t)r * DI + kb + c8 * 8);
        }
        CP_COMMIT();
    };

    load_stage(0, kb0);
    int quad = lane >> 3, lrow = lane & 7;

    for (int kc = 0; kc < PKC; kc++) {
        if (kc + 1 < PKC) { load_stage((kc + 1) & 1, kb0 + (kc + 1) * 64); CP_WAIT(1); }
        else CP_WAIT(0);
        __syncthreads();
        uint32_t base = sb + (kc & 1) * ST;
#pragma unroll
        for (int ks = 0; ks < 4; ks++) {
            int k16 = ks * 16;
            uint32_t aH[4];
            {
                int row = wm * 16 + (quad & 1) * 8 + lrow;
                ldsm4(aH, base + (uint32_t)(row * PTS + k16 + (quad >> 1) * 8) * 2);
            }
            uint32_t bH[6][2];
#pragma unroll
            for (int np = 0; np < 3; np++) {
                int nrow = wn * 48 + np * 16 + (quad >> 1) * 8 + lrow;
                uint32_t t[4];
                ldsm4(t, base + OB + (uint32_t)(nrow * PTS + k16 + (quad & 1) * 8) * 2);
                bH[np*2][0] = t[0]; bH[np*2][1] = t[1];
                bH[np*2+1][0] = t[2]; bH[np*2+1][1] = t[3];
            }
#pragma unroll
            for (int nt = 0; nt < 6; nt++)
                mma16816(d[nt], aH, bH[nt]);
        }
        __syncthreads();
    }

    float* pout = g_ppart[kspl];
#pragma unroll
    for (int nt = 0; nt < 6; nt++) {
        int row = m0 + wm * 16 + (lane >> 2);
        int col = wn * 48 + nt * 8 + (lane & 3) * 2;
        float2 v0 = {d[nt][0], d[nt][1]};
        float2 v1 = {d[nt][2], d[nt][3]};
        *(float2*)&pout[(size_t)row * 96 + col] = v0;
        *(float2*)&pout[(size_t)(row + 8) * 96 + col] = v1;
    }
}

__global__ __launch_bounds__(256)
void params_fix_kernel()
{
    int idx = blockIdx.x * 256 + threadIdx.x;
    int row = idx / 96, col = idx - row * 96;
    float s = g_ppart[0][idx] + g_ppart[1][idx] + g_ppart[2][idx] + g_ppart[3][idx];
    g_params[idx] = s;
    if (col < 64)
        g_dinh[(size_t)row * 64 + col] = __float2half_rn(s);
}

// ---------------- delta mma: g_delta[m][d] = softplus(delta_in @ Wdt + bdt) ----------------
__global__ __launch_bounds__(256)
void delta_mma_kernel(const float* __restrict__ bdt)
{
    __shared__ __align__(16) char ds[2 * 128 * PTS * 2];
    const uint32_t OB = 128 * PTS * 2;
    uint32_t sb = smem_to_u32(ds);

    int tid = threadIdx.x;
    int lane = tid & 31, wid = tid >> 5;
    int wm = wid & 3, wn = wid >> 2;
    int n0 = blockIdx.x * 128;
    int m0 = blockIdx.y * 128;

#pragma unroll
    for (int it = 0; it < 4; it++) {
        int u = tid + it * 256;
        int r = u >> 3, c8 = u & 7;
        CP_ASYNC16(sb + (uint32_t)(r * PTS + c8 * 8) * 2,
                   g_dinh + (size_t)(m0 + r) * 64 + c8 * 8);
    }
#pragma unroll
    for (int it = 0; it < 4; it++) {
        int u = tid + it * 256;
        int r = u >> 3, c8 = u & 7;
        CP_ASYNC16(sb + OB + (uint32_t)(r * PTS + c8 * 8) * 2,
                   g_Wdth + (size_t)(n0 + r) * 64 + c8 * 8);
    }
    CP_COMMIT();

    float d[2][8][4];
#pragma unroll
    for (int mt = 0; mt < 2; mt++)
#pragma unroll
        for (int nt = 0; nt < 8; nt++)
#pragma unroll
            for (int i = 0; i < 4; i++) d[mt][nt][i] = 0.f;

    CP_WAIT(0);
    __syncthreads();

    int quad = lane >> 3, lrow = lane & 7;
#pragma unroll
    for (int ks = 0; ks < 4; ks++) {
        int k16 = ks * 16;
        uint32_t aH[2][4];
#pragma unroll
        for (int mt = 0; mt < 2; mt++) {
            int row = wm * 32 + mt * 16 + (quad & 1) * 8 + lrow;
            ldsm4(aH[mt], sb + (uint32_t)(row * PTS + k16 + (quad >> 1) * 8) * 2);
        }
        uint32_t bH[8][2];
#pragma unroll
        for (int np = 0; np < 4; np++) {
            int nrow = wn * 64 + np * 16 + (quad >> 1) * 8 + lrow;
            uint32_t t[4];
            ldsm4(t, sb + OB + (uint32_t)(nrow * PTS + k16 + (quad & 1) * 8) * 2);
            bH[np*2][0] = t[0]; bH[np*2][1] = t[1];
            bH[np*2+1][0] = t[2]; bH[np*2+1][1] = t[3];
        }
#pragma unroll
        for (int mt = 0; mt < 2; mt++)
#pragma unroll
            for (int nt = 0; nt < 8; nt++)
                mma16816(d[mt][nt], aH[mt], bH[nt]);
    }

#pragma unroll
    for (int mt = 0; mt < 2; mt++)
#pragma unroll
        for (int nt = 0; nt < 8; nt++) {
            int row = m0 + wm * 32 + mt * 16 + (lane >> 2);
            int col = n0 + wn * 64 + nt * 8 + (lane & 3) * 2;
            float b0 = bdt[col], b1 = bdt[col + 1];
#pragma unroll
            for (int h = 0; h < 2; h++) {
                float t0 = d[mt][nt][h*2+0] + b0;
                float t1 = d[mt][nt][h*2+1] + b1;
                float2 v;
                v.x = fmaxf(t0, 0.f) + log1pf(__expf(-fabsf(t0)));
                v.y = fmaxf(t1, 0.f) + log1pf(__expf(-fabsf(t1)));
                *(float2*)&g_delta[(size_t)(row + h*8) * DI + col] = v;
            }
        }
}

// ---------------- selective scan: 8 lanes/channel, 2 states/lane; u fp16 in, y fp16 out ----------------
__global__ __launch_bounds__(128, 8)
void scan_kernel(const float* __restrict__ A_log, const float* __restrict__ Dp)
{
    __shared__ float2 sh_duu[32][16];
    __shared__ float  sh_bc[32][32];
    __shared__ float  sh_y[32][16];
    int tid = threadIdx.x;
    int lane = tid & 31, w = tid >> 5;
    int gch0 = blockIdx.x * 16;
    int b  = gch0 / DI;
    int d0 = gch0 % DI;
    int q  = lane & 7;
    int ch = w * 4 + (lane >> 3);
    int d  = d0 + ch;

    float an0, an1;
    {
        float2 al = *(const float2*)&A_log[(size_t)d * DSTATE + 2 * q];
        an0 = -__expf(al.x) * 1.44269504f;
        an1 = -__expf(al.y) * 1.44269504f;
    }
    float dpv = Dp[d];
    float s0 = 0.f, s1 = 0.f;

    const float*  dmb = g_delta + (size_t)b * SS * DI + d0;
    const __half* umb = g_xbch + (size_t)b * SS * DI + d0;
    const float*  pmb = g_params + (size_t)b * SS * 96 + 64;
    __half* ymb = g_yh + (size_t)b * SS * DI + d0;

    for (int t0 = 0; t0 < SS; t0 += 32) {
#pragma unroll
        for (int k = 0; k < 4; k++) {
            int idx = tid + k * 128;
            int i = idx >> 4, j = idx & 15;
            size_t off = (size_t)(t0 + i) * DI + j;
            sh_duu[i][j] = make_float2(dmb[off], __half2float(umb[off]));
        }
#pragma unroll
        for (int k = 0; k < 8; k++) {
            int idx = tid + k * 128;
            int i = idx >> 5, j = idx & 31;
            sh_bc[i][j] = pmb[(size_t)(t0 + i) * 96 + j];
        }
        __syncthreads();

#pragma unroll 4
        for (int i = 0; i < 32; i++) {
            float2 duu = sh_duu[i][ch];
            float2 bq = *(float2*)&sh_bc[i][2 * q];
            float2 cq = *(float2*)&sh_bc[i][16 + 2 * q];
            float du = duu.x * duu.y;
            float e0 = exp2f(duu.x * an0);
            float e1 = exp2f(duu.x * an1);
            s0 = fmaf(e0, s0, du * bq.x);
            s1 = fmaf(e1, s1, du * bq.y);
            float acc = fmaf(s1, cq.y, s0 * cq.x);
            acc += __shfl_xor_sync(0xffffffffu, acc, 1);
            acc += __shfl_xor_sync(0xffffffffu, acc, 2);
            acc += __shfl_xor_sync(0xffffffffu, acc, 4);
            if (q == 0) sh_y[i][ch] = fmaf(duu.y, dpv, acc);
        }
        __syncthreads();
#pragma unroll
        for (int k = 0; k < 2; k++) {
            int idx = tid + k * 128;
            int i = idx >> 3, j = idx & 7;
            __half2 hv = __floats2half2_rn(sh_y[i][2*j], sh_y[i][2*j + 1]);
            *(__half2*)&ymb[(size_t)(t0 + i) * DI + 2*j] = hv;
        }
    }
}

// ---------------- host: tensor-map plumbing ----------------
typedef CUresult (*EncodeFn)(CUtensorMap*, CUtensorMapDataType, cuuint32_t, void*,
                             const cuuint64_t*, const cuuint64_t*, const cuuint32_t*,
                             const cuuint32_t*, CUtensorMapInterleave, CUtensorMapSwizzle,
                             CUtensorMapL2promotion, CUtensorMapFloatOOBfill);

static EncodeFn get_encode_fn()
{
    static EncodeFn fn = nullptr;
    if (!fn) {
        void* p = nullptr;
        cudaDriverEntryPointQueryResult qr;
        cudaGetDriverEntryPointByVersion("cuTensorMapEncodeTiled", &p, 12000,
                                         cudaEnableDefault, &qr);
        fn = (EncodeFn)p;
    }
    return fn;
}

static void make_tm(CUtensorMap* tm, void* gaddr, uint64_t kdim, uint64_t rows)
{
    cuuint64_t dims[2]    = {kdim, rows};
    cuuint64_t strides[1] = {kdim * 2};
    cuuint32_t box[2]     = {64, 128};
    cuuint32_t es[2]      = {1, 1};
    get_encode_fn()(tm, CU_TENSOR_MAP_DATA_TYPE_FLOAT16, 2, gaddr,
                    dims, strides, box, es,
                    CU_TENSOR_MAP_INTERLEAVE_NONE, CU_TENSOR_MAP_SWIZZLE_128B,
                    CU_TENSOR_MAP_L2_PROMOTION_L2_128B,
                    CU_TENSOR_MAP_FLOAT_OOB_FILL_NONE);
}

// ---------------- launch ----------------
extern "C" void kernel_launch(void* const* d_in, const int* in_sizes, int n_in,
                              void* d_out, int out_size)
{
    (void)in_sizes; (void)n_in; (void)out_size;
    const float* x     = (const float*)d_in[0];
    const float* Win   = (const float*)d_in[1];
    const float* Wconv = (const float*)d_in[2];
    const float* bconv = (const float*)d_in[3];
    const float* Wx    = (const float*)d_in[4];
    const float* Wdt   = (const float*)d_in[5];
    const float* bdt   = (const float*)d_in[6];
    const float* A_log = (const float*)d_in[7];
    const float* Dp    = (const float*)d_in[8];
    const float* Wout  = (const float*)d_in[9];
    float* out = (float*)d_out;

    void *pA1h, *pB1h, *pA3h, *pB3h;
    cudaGetSymbolAddress(&pA1h, g_A1h);
    cudaGetSymbolAddress(&pB1h, g_B1h);
    cudaGetSymbolAddress(&pA3h, g_A3h);
    cudaGetSymbolAddress(&pB3h, g_B3h);

    CUtensorMap tmA1, tmB1, tmA3, tmB3;
    make_tm(&tmA1, pA1h, DM, MM);
    make_tm(&tmB1, pB1h, DM, 2*DI);
    make_tm(&tmA3, pA3h, DI, MM);
    make_tm(&tmB3, pB3h, DI, DM);

    cudaFuncSetAttribute(mma_gemm_kernel<1>, cudaFuncAttributeMaxDynamicSharedMemorySize, GSMEM_B);
    cudaFuncSetAttribute(mma_gemm_kernel<3>, cudaFuncAttributeMaxDynamicSharedMemorySize, GSMEM_B);

    static cudaStream_t s2 = nullptr;
    static cudaEvent_t evA = nullptr, evB = nullptr;
    if (!s2) {
        cudaStreamCreateWithFlags(&s2, cudaStreamNonBlocking);
        cudaEventCreateWithFlags(&evA, cudaEventDisableTiming);
        cudaEventCreateWithFlags(&evB, cudaEventDisableTiming);
    }

    prep_kernel<<<PREP_BLOCKS, 256>>>(x, Win, Wx, Wdt, Wout);

    // fork: z-half of GEMM1 on s2 (only needed at gate)
    cudaEventRecord(evA, 0);
    cudaStreamWaitEvent(s2, evA, 0);

    mma_gemm_kernel<1><<<dim3(16, 32), 256, GSMEM_B>>>(tmA1, tmB1, nullptr, 0);      // x half
    mma_gemm_kernel<1><<<dim3(16, 32), 256, GSMEM_B, s2>>>(tmA1, tmB1, nullptr, DI); // z half

    conv_kernel<<<dim3(SS / 16, DI / 256, BB), 128>>>(Wconv, bconv);
    params_mma_kernel<<<dim3(128, PKS), 128>>>();
    params_fix_kernel<<<MM * 96 / 256, 256>>>();
    delta_mma_kernel<<<dim3(16, 32), 256>>>(bdt);
    scan_kernel<<<256, 128>>>(A_log, Dp);

    // join: gate needs z from s2
    cudaEventRecord(evB, s2);
    cudaStreamWaitEvent(0, evB, 0);

    gate_convert_kernel<<<8192, 256>>>();
    mma_gemm_kernel<3><<<dim3(8, 32), 256, GSMEM_B>>>(tmA3, tmB3, out, 0);
}